// round 5
// baseline (speedup 1.0000x reference)
#include <cuda_runtime.h>
#include <math.h>
#include <stdint.h>

#define BB 2
#define LL 401
#define DD 128
#define NBI (BB*LL)   // 802
#define PAD 136       // k2 smem row pitch (floats): 8-float shift per row

__device__ float g_tmp[(size_t)NBI * DD * DD];   // 52.6 MB: tmp[b,i,k,e]
__device__ float g_C[(size_t)BB * LL * LL];      // contact before symmetrization

// ---------------------------------------------------------------------------
// Helpers
// ---------------------------------------------------------------------------
__device__ __forceinline__ float tf32r(float f) {
    uint32_t u;
    asm("cvt.rna.tf32.f32 %0, %1;" : "=r"(u) : "f"(f));
    return __uint_as_float(u);
}
__device__ __forceinline__ uint32_t fu(float f) { return __float_as_uint(f); }

__device__ __forceinline__ void mma_tf32(float c[4],
                                         uint32_t a0, uint32_t a1, uint32_t a2, uint32_t a3,
                                         uint32_t b0, uint32_t b1)
{
    asm volatile(
        "mma.sync.aligned.m16n8k8.row.col.f32.tf32.tf32.f32 "
        "{%0,%1,%2,%3}, {%4,%5,%6,%7}, {%8,%9}, {%0,%1,%2,%3};"
        : "+f"(c[0]), "+f"(c[1]), "+f"(c[2]), "+f"(c[3])
        : "r"(a0), "r"(a1), "r"(a2), "r"(a3), "r"(b0), "r"(b1));
}

// ---------------------------------------------------------------------------
// Kernel 1 (tf32 mma): tmp[bi][k][e] = sum_d x[bi][d] * W_bil[k][d][e]
// bi-tile = 64 rows -> smem ~101 KB -> 2 CTAs/SM.
// Warps 4(wj) x 2(wk); warp tile 16m x 64n.
// ---------------------------------------------------------------------------
__global__ __launch_bounds__(256, 2) void k1_tmp(const float* __restrict__ x,
                                                 const float* __restrict__ Wb)
{
    extern __shared__ float sm[];
    float* Xs = sm;              // [64][132]  x rows (tf32)
    float* Ws = sm + 64 * 132;   // [128][132] Wk[d][e] (tf32)

    const int k   = blockIdx.x;
    const int bi0 = blockIdx.y * 64;
    const int tid = threadIdx.x, tx = tid & 31, wid = tid >> 5;
    const int wj  = wid & 3, wk = wid >> 2;
    const int g   = tx >> 2, c = tx & 3;

    const float* Wk = Wb + (size_t)k * DD * DD;
    #pragma unroll
    for (int s = 0; s < 8; ++s) {
        int v = tid + (s << 8);              // float4 index, 2048 total
        int row = v >> 5, col4 = (v & 31) << 2;
        float* d = &Xs[row * 132 + col4];
        int bi = bi0 + row;
        if (bi < NBI) {
            float4 t = *(const float4*)&x[(size_t)bi * DD + col4];
            d[0] = tf32r(t.x); d[1] = tf32r(t.y); d[2] = tf32r(t.z); d[3] = tf32r(t.w);
        } else {
            d[0] = 0.f; d[1] = 0.f; d[2] = 0.f; d[3] = 0.f;
        }
    }
    #pragma unroll
    for (int s = 0; s < 16; ++s) {
        int v = tid + (s << 8);              // 4096 float4 units
        int row = v >> 5, col4 = (v & 31) << 2;
        float4 w = *(const float4*)&Wk[row * DD + col4];
        float* e = &Ws[row * 132 + col4];
        e[0] = tf32r(w.x); e[1] = tf32r(w.y); e[2] = tf32r(w.z); e[3] = tf32r(w.w);
    }
    __syncthreads();

    float acc[8][4];
    #pragma unroll
    for (int nt = 0; nt < 8; ++nt)
        #pragma unroll
        for (int u = 0; u < 4; ++u) acc[nt][u] = 0.0f;

    const int arow = wj * 16, bcol = wk * 64;

    #pragma unroll
    for (int d0 = 0; d0 < DD; d0 += 8) {
        const float* Ar = &Xs[(arow + g) * 132 + d0];
        uint32_t a0 = fu(Ar[c]);
        uint32_t a1 = fu(Ar[8 * 132 + c]);
        uint32_t a2 = fu(Ar[c + 4]);
        uint32_t a3 = fu(Ar[8 * 132 + c + 4]);
        #pragma unroll
        for (int nt = 0; nt < 8; ++nt) {
            uint32_t b0 = fu(Ws[(d0 + c) * 132 + bcol + nt * 8 + g]);
            uint32_t b1 = fu(Ws[(d0 + c + 4) * 132 + bcol + nt * 8 + g]);
            mma_tf32(acc[nt], a0, a1, a2, a3, b0, b1);
        }
    }

    #pragma unroll
    for (int nt = 0; nt < 8; ++nt) {
        int r0  = bi0 + arow + g;
        int col = bcol + nt * 8 + 2 * c;
        if (r0 < NBI) {
            float2 v = {acc[nt][0], acc[nt][1]};
            *(float2*)&g_tmp[(size_t)r0 * (DD * DD) + k * DD + col] = v;
        }
        int r1 = r0 + 8;
        if (r1 < NBI) {
            float2 v = {acc[nt][2], acc[nt][3]};
            *(float2*)&g_tmp[(size_t)r1 * (DD * DD) + k * DD + col] = v;
        }
    }
}

// ---------------------------------------------------------------------------
// Kernel 2: per (b,i) CTA, fused tf32-mma pipeline.
// Interleaved column layout: within each 8-col group, logical col z sits at
// pos(z) = ((z&3)<<1) | (z>>2), so frag pairs (c, c+4) are adjacent -> LDS.64.
// Tiles: j0 = 0,128,256,384 with m-rows {128,128,128,32} (tail skip).
// ---------------------------------------------------------------------------
__global__ __launch_bounds__(256, 1) void k2_fused(
    const float* __restrict__ x,    const float* __restrict__ b_bil,
    const float* __restrict__ ln_g, const float* __restrict__ ln_b,
    const float* __restrict__ W1,   const float* __restrict__ b1,
    const float* __restrict__ w2,   const float* __restrict__ b2)
{
    extern __shared__ float sm[];
    float* Ts  = sm;                 // [128][PAD] tmp_i (tf32, interleaved cols)
    float* W1s = Ts + 128 * PAD;     // [128][PAD] W1[e][d] (interleaved d)
    float* Xs  = W1s + 128 * PAD;    // [128][PAD] x_j tile / H (interleaved)
    float* cv  = Xs + 128 * PAD;
    float* bbs = cv;        float* lgs = cv + 128; float* lbs = cv + 256;
    float* b1s = cv + 384;  float* w2s = cv + 512;
    float2* redA = (float2*)(cv + 640);  // [128][2] (s1,s2) per half
    float*  redB = (float*)(cv + 640 + 512); // [128][2]

    const int bi  = blockIdx.x;
    const int b   = bi / LL;
    const int tid = threadIdx.x, tx = tid & 31, wid = tid >> 5;
    const int wj  = wid & 3, wk = wid >> 2;
    const int g   = tx >> 2, c = tx & 3;
    const int arow = wj * 32, bcol = wk * 64;
    // permuted positions of this thread's accumulator columns within 8-group
    const int z0 = 2 * c, z1 = 2 * c + 1;
    const int p0 = ((z0 & 3) << 1) | (z0 >> 2);
    const int p1 = ((z1 & 3) << 1) | (z1 >> 2);

    // ---- Load tmp_i and W1 into interleaved smem (tf32-rounded) ----
    const float* tp = g_tmp + (size_t)bi * DD * DD;
    #pragma unroll
    for (int s = 0; s < 8; ++s) {
        int v = tid + (s << 8);          // 8-float units, 2048 total
        int row = v >> 4, seg = (v & 15) << 3;
        {
            const float* srcp = &tp[row * DD + seg];
            float4 u0 = *(const float4*)srcp;
            float4 u1 = *(const float4*)(srcp + 4);
            float2* d = (float2*)&Ts[row * PAD + seg];
            d[0] = make_float2(tf32r(u0.x), tf32r(u1.x));
            d[1] = make_float2(tf32r(u0.y), tf32r(u1.y));
            d[2] = make_float2(tf32r(u0.z), tf32r(u1.z));
            d[3] = make_float2(tf32r(u0.w), tf32r(u1.w));
        }
        {
            const float* srcp = &W1[row * DD + seg];
            float4 u0 = *(const float4*)srcp;
            float4 u1 = *(const float4*)(srcp + 4);
            float2* d = (float2*)&W1s[row * PAD + seg];
            d[0] = make_float2(tf32r(u0.x), tf32r(u1.x));
            d[1] = make_float2(tf32r(u0.y), tf32r(u1.y));
            d[2] = make_float2(tf32r(u0.z), tf32r(u1.z));
            d[3] = make_float2(tf32r(u0.w), tf32r(u1.w));
        }
    }
    if (tid < 128) {
        bbs[tid] = b_bil[tid]; lgs[tid] = ln_g[tid]; lbs[tid] = ln_b[tid];
        b1s[tid] = b1[tid];    w2s[tid] = w2[tid];
    }
    const float b2v = b2[0];
    const float* xb = x + (size_t)b * LL * DD;
    float* Crow = g_C + (size_t)bi * LL;
    __syncthreads();

    #pragma unroll 1
    for (int t = 0; t < 4; ++t) {
        const int j0 = t * 128;
        const int mrows = (t == 3) ? 32 : 128;
        const bool active = (arow < mrows);

        // ---- Load x_j tile (tf32, zero-pad, interleaved) ----
        #pragma unroll
        for (int s = 0; s < 8; ++s) {
            int v = tid + (s << 8);
            int row = v >> 4, seg = (v & 15) << 3;
            int j = j0 + row;
            float2* d = (float2*)&Xs[row * PAD + seg];
            if (j < LL) {
                const float* srcp = &xb[(size_t)j * DD + seg];
                float4 u0 = *(const float4*)srcp;
                float4 u1 = *(const float4*)(srcp + 4);
                d[0] = make_float2(tf32r(u0.x), tf32r(u1.x));
                d[1] = make_float2(tf32r(u0.y), tf32r(u1.y));
                d[2] = make_float2(tf32r(u0.z), tf32r(u1.z));
                d[3] = make_float2(tf32r(u0.w), tf32r(u1.w));
            } else {
                d[0] = make_float2(0.f, 0.f); d[1] = make_float2(0.f, 0.f);
                d[2] = make_float2(0.f, 0.f); d[3] = make_float2(0.f, 0.f);
            }
        }
        __syncthreads();

        float acc[2][8][4];
        float s1[4], s2[4];
        if (active) {
            // ---- Phase A: pair = X @ Ts^T ----
            #pragma unroll
            for (int mf = 0; mf < 2; ++mf)
                #pragma unroll
                for (int nt = 0; nt < 8; ++nt)
                    #pragma unroll
                    for (int u = 0; u < 4; ++u) acc[mf][nt][u] = 0.0f;

            #pragma unroll
            for (int e0 = 0; e0 < DD; e0 += 8) {
                uint32_t a[2][4];
                #pragma unroll
                for (int mf = 0; mf < 2; ++mf) {
                    const float* Ar = &Xs[(arow + mf * 16 + g) * PAD + e0 + 2 * c];
                    float2 pq = *(const float2*)Ar;
                    float2 rq = *(const float2*)(Ar + 8 * PAD);
                    a[mf][0] = fu(pq.x); a[mf][1] = fu(rq.x);
                    a[mf][2] = fu(pq.y); a[mf][3] = fu(rq.y);
                }
                #pragma unroll
                for (int nt = 0; nt < 8; ++nt) {
                    float2 bv = *(const float2*)&Ts[(bcol + nt * 8 + g) * PAD + e0 + 2 * c];
                    uint32_t b0 = fu(bv.x), b1r = fu(bv.y);
                    mma_tf32(acc[0][nt], a[0][0], a[0][1], a[0][2], a[0][3], b0, b1r);
                    mma_tf32(acc[1][nt], a[1][0], a[1][1], a[1][2], a[1][3], b0, b1r);
                }
            }

            // ---- LN stats (rows: lr = mf*2 + half8) ----
            #pragma unroll
            for (int lr = 0; lr < 4; ++lr) { s1[lr] = 0.f; s2[lr] = 0.f; }
            #pragma unroll
            for (int mf = 0; mf < 2; ++mf)
                #pragma unroll
                for (int nt = 0; nt < 8; ++nt) {
                    int col = bcol + nt * 8 + 2 * c;
                    float bb0 = bbs[col], bb1 = bbs[col + 1];
                    acc[mf][nt][0] += bb0; acc[mf][nt][1] += bb1;
                    acc[mf][nt][2] += bb0; acc[mf][nt][3] += bb1;
                    s1[mf * 2]     += acc[mf][nt][0] + acc[mf][nt][1];
                    s2[mf * 2]     += acc[mf][nt][0] * acc[mf][nt][0] + acc[mf][nt][1] * acc[mf][nt][1];
                    s1[mf * 2 + 1] += acc[mf][nt][2] + acc[mf][nt][3];
                    s2[mf * 2 + 1] += acc[mf][nt][2] * acc[mf][nt][2] + acc[mf][nt][3] * acc[mf][nt][3];
                }
            #pragma unroll
            for (int off = 1; off <= 2; off <<= 1)
                #pragma unroll
                for (int lr = 0; lr < 4; ++lr) {
                    s1[lr] += __shfl_xor_sync(0xffffffffu, s1[lr], off);
                    s2[lr] += __shfl_xor_sync(0xffffffffu, s2[lr], off);
                }
            if (c == 0) {
                #pragma unroll
                for (int lr = 0; lr < 4; ++lr) {
                    int row = arow + (lr >> 1) * 16 + (lr & 1) * 8 + g;
                    redA[row * 2 + wk] = make_float2(s1[lr], s2[lr]);
                }
            }
        }
        __syncthreads();

        if (active) {
            float mu[4], rs[4];
            #pragma unroll
            for (int lr = 0; lr < 4; ++lr) {
                int row = arow + (lr >> 1) * 16 + (lr & 1) * 8 + g;
                float2 rA = redA[row * 2 + 0], rB = redA[row * 2 + 1];
                float S1 = rA.x + rB.x, S2 = rA.y + rB.y;
                mu[lr] = S1 * (1.0f / 128.0f);
                rs[lr] = rsqrtf(S2 * (1.0f / 128.0f) - mu[lr] * mu[lr] + 1e-5f);
            }
            // ---- Write H (tf32, interleaved positions) into Xs ----
            #pragma unroll
            for (int mf = 0; mf < 2; ++mf)
                #pragma unroll
                for (int nt = 0; nt < 8; ++nt) {
                    int colb = bcol + nt * 8;
                    int col = colb + 2 * c;
                    float lg0 = lgs[col], lg1 = lgs[col + 1];
                    float lb0 = lbs[col], lb1 = lbs[col + 1];
                    int lr0 = mf * 2, lr1 = mf * 2 + 1;
                    int r0 = arow + mf * 16 + g;
                    Xs[r0 * PAD + colb + p0] = tf32r((acc[mf][nt][0] - mu[lr0]) * rs[lr0] * lg0 + lb0);
                    Xs[r0 * PAD + colb + p1] = tf32r((acc[mf][nt][1] - mu[lr0]) * rs[lr0] * lg1 + lb1);
                    Xs[(r0 + 8) * PAD + colb + p0] = tf32r((acc[mf][nt][2] - mu[lr1]) * rs[lr1] * lg0 + lb0);
                    Xs[(r0 + 8) * PAD + colb + p1] = tf32r((acc[mf][nt][3] - mu[lr1]) * rs[lr1] * lg1 + lb1);
                }
        }
        __syncthreads();

        if (active) {
            // ---- Phase B: o = H @ W1^T ----
            #pragma unroll
            for (int mf = 0; mf < 2; ++mf)
                #pragma unroll
                for (int nt = 0; nt < 8; ++nt)
                    #pragma unroll
                    for (int u = 0; u < 4; ++u) acc[mf][nt][u] = 0.0f;

            #pragma unroll
            for (int d0 = 0; d0 < DD; d0 += 8) {
                uint32_t a[2][4];
                #pragma unroll
                for (int mf = 0; mf < 2; ++mf) {
                    const float* Ar = &Xs[(arow + mf * 16 + g) * PAD + d0 + 2 * c];
                    float2 pq = *(const float2*)Ar;
                    float2 rq = *(const float2*)(Ar + 8 * PAD);
                    a[mf][0] = fu(pq.x); a[mf][1] = fu(rq.x);
                    a[mf][2] = fu(pq.y); a[mf][3] = fu(rq.y);
                }
                #pragma unroll
                for (int nt = 0; nt < 8; ++nt) {
                    float2 bv = *(const float2*)&W1s[(bcol + nt * 8 + g) * PAD + d0 + 2 * c];
                    uint32_t b0 = fu(bv.x), b1r = fu(bv.y);
                    mma_tf32(acc[0][nt], a[0][0], a[0][1], a[0][2], a[0][3], b0, b1r);
                    mma_tf32(acc[1][nt], a[1][0], a[1][1], a[1][2], a[1][3], b0, b1r);
                }
            }

            // ---- Epilogue: bias, exact GELU, dot w2 ----
            float tsum[4] = {0.f, 0.f, 0.f, 0.f};
            #pragma unroll
            for (int mf = 0; mf < 2; ++mf)
                #pragma unroll
                for (int nt = 0; nt < 8; ++nt) {
                    int col = bcol + nt * 8 + 2 * c;
                    float c0 = b1s[col], c1 = b1s[col + 1];
                    float w0 = w2s[col], w1 = w2s[col + 1];
                    float v0 = acc[mf][nt][0] + c0, v1 = acc[mf][nt][1] + c1;
                    float v2 = acc[mf][nt][2] + c0, v3 = acc[mf][nt][3] + c1;
                    tsum[mf * 2]     += 0.5f * v0 * (1.0f + erff(v0 * 0.70710678118654752f)) * w0
                                      + 0.5f * v1 * (1.0f + erff(v1 * 0.70710678118654752f)) * w1;
                    tsum[mf * 2 + 1] += 0.5f * v2 * (1.0f + erff(v2 * 0.70710678118654752f)) * w0
                                      + 0.5f * v3 * (1.0f + erff(v3 * 0.70710678118654752f)) * w1;
                }
            #pragma unroll
            for (int off = 1; off <= 2; off <<= 1)
                #pragma unroll
                for (int lr = 0; lr < 4; ++lr)
                    tsum[lr] += __shfl_xor_sync(0xffffffffu, tsum[lr], off);
            if (c == 0) {
                #pragma unroll
                for (int lr = 0; lr < 4; ++lr) {
                    int row = arow + (lr >> 1) * 16 + (lr & 1) * 8 + g;
                    redB[row * 2 + wk] = tsum[lr];
                }
            }
        }
        __syncthreads();

        if (tid < 128) {
            int j = j0 + tid;
            if (j < LL) Crow[j] = redB[tid * 2] + redB[tid * 2 + 1] + b2v;
        }
        __syncthreads();
    }
}

// ---------------------------------------------------------------------------
// Kernel 3: out[b,i,j] = 0.5 * (C[b,i,j] + C[b,j,i])
// ---------------------------------------------------------------------------
__global__ void k3_sym(float* __restrict__ out)
{
    int idx = blockIdx.x * 256 + threadIdx.x;
    if (idx >= BB * LL * LL) return;
    int b  = idx / (LL * LL);
    int rm = idx - b * LL * LL;
    int i  = rm / LL, j = rm % LL;
    out[idx] = 0.5f * (g_C[idx] + g_C[((size_t)b * LL + j) * LL + i]);
}

// ---------------------------------------------------------------------------
extern "C" void kernel_launch(void* const* d_in, const int* in_sizes, int n_in,
                              void* d_out, int out_size)
{
    (void)in_sizes; (void)n_in; (void)out_size;
    const float* x     = (const float*)d_in[0];
    const float* W_bil = (const float*)d_in[1];
    const float* b_bil = (const float*)d_in[2];
    const float* ln_g  = (const float*)d_in[3];
    const float* ln_b  = (const float*)d_in[4];
    const float* W1    = (const float*)d_in[5];
    const float* b1    = (const float*)d_in[6];
    const float* w2    = (const float*)d_in[7];
    const float* b2    = (const float*)d_in[8];
    float* out = (float*)d_out;

    const int smem1 = (64 * 132 + 128 * 132) * 4;                    // ~101 KB, occ 2
    const int smem2 = (3 * 128 * PAD + 640 + 512 + 256) * 4;         // ~214.5 KB
    cudaFuncSetAttribute(k1_tmp,   cudaFuncAttributeMaxDynamicSharedMemorySize, smem1);
    cudaFuncSetAttribute(k2_fused, cudaFuncAttributeMaxDynamicSharedMemorySize, smem2);

    dim3 g1(128, (NBI + 63) / 64);   // 128 x 13
    k1_tmp<<<g1, 256, smem1>>>(x, W_bil);
    k2_fused<<<NBI, 256, smem2>>>(x, b_bil, ln_g, ln_b, W1, b1, w2, b2);

    int tot = BB * LL * LL;
    k3_sym<<<(tot + 255) / 256, 256>>>(out);
}

// round 6
// speedup vs baseline: 1.7932x; 1.7932x over previous
#include <cuda_runtime.h>
#include <cuda_fp16.h>
#include <math.h>
#include <stdint.h>

#define BB 2
#define LL 401
#define DD 128
#define NBI (BB*LL)   // 802
#define HP 68         // smem row pitch in half2 (136 halfs, 272 B)

__device__ __half g_tmp_h[(size_t)NBI * DD * DD];  // 26.3 MB: tmp[b,i,k,e] fp16
__device__ float  g_C[(size_t)BB * LL * LL];       // contact before symmetrization

// ---------------------------------------------------------------------------
__device__ __forceinline__ void mma_f16(float c[4],
                                        uint32_t a0, uint32_t a1, uint32_t a2, uint32_t a3,
                                        uint32_t b0, uint32_t b1)
{
    asm volatile(
        "mma.sync.aligned.m16n8k16.row.col.f32.f16.f16.f32 "
        "{%0,%1,%2,%3}, {%4,%5,%6,%7}, {%8,%9}, {%0,%1,%2,%3};"
        : "+f"(c[0]), "+f"(c[1]), "+f"(c[2]), "+f"(c[3])
        : "r"(a0), "r"(a1), "r"(a2), "r"(a3), "r"(b0), "r"(b1));
}
__device__ __forceinline__ uint32_t ldu32(const __half2* p) {
    return *(const uint32_t*)p;
}

// ---------------------------------------------------------------------------
// Kernel 1 (fp16 mma): tmp[bi][k][e] = sum_d x[bi][d] * W_bil[k][d][e]
// Per block: one k-slice, 128 bi rows. Warps 4(wj) x 2(wk), tile 32m x 64n.
// Xs: [128][HP] half2 (bi rows, d packed).  Wt: [128][HP] half2 (e rows, d packed).
// Wk arrives [d][e]; transposed via 2-stage smem staging.
// ---------------------------------------------------------------------------
#define K1_XS 0u
#define K1_WT 34816u
#define K1_SG 69632u        // staging: [128][128] halfs (32 KB)
#define K1_SMEM 102400u

__global__ __launch_bounds__(256, 2) void k1_tmp(const float* __restrict__ x,
                                                 const float* __restrict__ Wb)
{
    extern __shared__ char smc[];
    __half2* Xs   = (__half2*)(smc + K1_XS);
    __half2* Wt   = (__half2*)(smc + K1_WT);
    __half*  Sg   = (__half*) (smc + K1_SG);

    const int k   = blockIdx.x;
    const int bi0 = blockIdx.y * 128;
    const int tid = threadIdx.x, tx = tid & 31, wid = tid >> 5;
    const int wj  = wid & 3, wk = wid >> 2;
    const int g   = tx >> 2, c = tx & 3;
    const int arow = wj * 32, bcol = wk * 64;

    const float* Wk = Wb + (size_t)k * DD * DD;

    // ---- Stage 1: Wk[d][e] -> Sg[d][e] as fp16 (coalesced, conflict-free) ----
    #pragma unroll
    for (int s = 0; s < 16; ++s) {
        int v = tid + (s << 8);          // float4 units, 4096
        int d = v >> 5, e4 = (v & 31) << 2;
        float4 w = *(const float4*)&Wk[d * DD + e4];
        __half2* dst = (__half2*)&Sg[d * 128 + e4];
        dst[0] = __floats2half2_rn(w.x, w.y);
        dst[1] = __floats2half2_rn(w.z, w.w);
    }
    // ---- x rows -> Xs (half2 along d) ----
    #pragma unroll
    for (int s = 0; s < 16; ++s) {
        int v = tid + (s << 8);
        int row = v >> 5, d4 = (v & 31) << 2;
        int bi = bi0 + row;
        __half2 h0, h1;
        if (bi < NBI) {
            float4 t = *(const float4*)&x[(size_t)bi * DD + d4];
            h0 = __floats2half2_rn(t.x, t.y);
            h1 = __floats2half2_rn(t.z, t.w);
        } else {
            h0 = __floats2half2_rn(0.f, 0.f); h1 = h0;
        }
        Xs[row * HP + (d4 >> 1)]     = h0;
        Xs[row * HP + (d4 >> 1) + 1] = h1;
    }
    __syncthreads();

    // ---- Stage 2: Sg[d][e] -> Wt[e][d-pairs] (reads conflict-free; writes <=4-way) ----
    #pragma unroll
    for (int s = 0; s < 32; ++s) {
        int v = tid + (s << 8);          // half2 outputs, 8192
        int e = v & 127, d2 = v >> 7;
        __half lo = Sg[(2 * d2) * 128 + e];
        __half hi = Sg[(2 * d2 + 1) * 128 + e];
        Wt[e * HP + d2] = __halves2half2(lo, hi);
    }
    __syncthreads();

    float acc[2][8][4];
    #pragma unroll
    for (int mf = 0; mf < 2; ++mf)
        #pragma unroll
        for (int nt = 0; nt < 8; ++nt)
            #pragma unroll
            for (int u = 0; u < 4; ++u) acc[mf][nt][u] = 0.0f;

    #pragma unroll
    for (int kc = 0; kc < 8; ++kc) {     // 8 chunks of k16
        int o = kc * 8;
        uint32_t a[2][4];
        #pragma unroll
        for (int mf = 0; mf < 2; ++mf) {
            const __half2* Ar = &Xs[(arow + mf * 16 + g) * HP + o];
            a[mf][0] = ldu32(Ar + c);
            a[mf][1] = ldu32(Ar + 8 * HP + c);
            a[mf][2] = ldu32(Ar + c + 4);
            a[mf][3] = ldu32(Ar + 8 * HP + c + 4);
        }
        #pragma unroll
        for (int nt = 0; nt < 8; ++nt) {
            const __half2* Br = &Wt[(bcol + nt * 8 + g) * HP + o];
            uint32_t b0 = ldu32(Br + c);
            uint32_t b1 = ldu32(Br + c + 4);
            mma_f16(acc[0][nt], a[0][0], a[0][1], a[0][2], a[0][3], b0, b1);
            mma_f16(acc[1][nt], a[1][0], a[1][1], a[1][2], a[1][3], b0, b1);
        }
    }

    #pragma unroll
    for (int mf = 0; mf < 2; ++mf)
        #pragma unroll
        for (int nt = 0; nt < 8; ++nt) {
            int r0  = bi0 + arow + mf * 16 + g;
            int col = bcol + nt * 8 + 2 * c;
            if (r0 < NBI)
                *(__half2*)&g_tmp_h[(size_t)r0 * (DD * DD) + k * DD + col] =
                    __floats2half2_rn(acc[mf][nt][0], acc[mf][nt][1]);
            int r1 = r0 + 8;
            if (r1 < NBI)
                *(__half2*)&g_tmp_h[(size_t)r1 * (DD * DD) + k * DD + col] =
                    __floats2half2_rn(acc[mf][nt][2], acc[mf][nt][3]);
        }
}

// ---------------------------------------------------------------------------
// Kernel 2 (fp16 mma): per (b,i) CTA, fused, j-tile = 128 rows.
// Warps 4(wj) x 2(wk), warp tile 32m x 64n.
//   pair = X_b @ tmp_i^T + b_bil -> LayerNorm (fp32) -> H (fp16, in Xs)
//   o = H @ W1^T + b1 -> exact GELU -> dot(w2) -> g_C
// ---------------------------------------------------------------------------
#define K2_TS 0u
#define K2_WS 34816u
#define K2_XS 69632u
#define K2_CV 104448u        // 640 floats
#define K2_RA 107008u        // float2[256]
#define K2_RB 109056u        // float[256]
#define K2_SMEM 110080u

__global__ __launch_bounds__(256, 2) void k2_fused(
    const float* __restrict__ x,    const float* __restrict__ b_bil,
    const float* __restrict__ ln_g, const float* __restrict__ ln_b,
    const float* __restrict__ W1,   const float* __restrict__ b1,
    const float* __restrict__ w2,   const float* __restrict__ b2)
{
    extern __shared__ char smc[];
    __half2* Ts  = (__half2*)(smc + K2_TS);   // [128][HP] tmp_i (k rows, e packed)
    __half2* W1s = (__half2*)(smc + K2_WS);   // [128][HP] W1 (e rows, d packed)
    __half2* Xs  = (__half2*)(smc + K2_XS);   // [128][HP] x_j / H (j rows, e|d packed)
    float* cv  = (float*)(smc + K2_CV);
    float* bbs = cv;        float* lgs = cv + 128; float* lbs = cv + 256;
    float* b1s = cv + 384;  float* w2s = cv + 512;
    float2* redA = (float2*)(smc + K2_RA);    // [128][2] (s1,s2)
    float*  redB = (float*) (smc + K2_RB);    // [128][2]

    const int bi  = blockIdx.x;
    const int b   = bi / LL;
    const int tid = threadIdx.x, tx = tid & 31, wid = tid >> 5;
    const int wj  = wid & 3, wk = wid >> 2;
    const int g   = tx >> 2, c = tx & 3;
    const int arow = wj * 32, bcol = wk * 64;

    // ---- Load tmp_i (already fp16: raw copy) and W1 (convert) ----
    const __half* tp = g_tmp_h + (size_t)bi * DD * DD;
    #pragma unroll
    for (int s = 0; s < 8; ++s) {
        int v = tid + (s << 8);          // 8-half units, 2048
        int row = v >> 4, seg = (v & 15) << 3;   // halfs offset
        // tmp_i: 16B raw copy
        uint4 tv = *(const uint4*)&tp[row * DD + seg];
        *(uint4*)((char*)Ts + row * 272 + seg * 2) = tv;
        // W1: convert 8 floats
        const float* wp = &W1[row * DD + seg];
        float4 u0 = *(const float4*)wp;
        float4 u1 = *(const float4*)(wp + 4);
        __half2* d = (__half2*)((char*)W1s + row * 272 + seg * 2);
        d[0] = __floats2half2_rn(u0.x, u0.y);
        d[1] = __floats2half2_rn(u0.z, u0.w);
        d[2] = __floats2half2_rn(u1.x, u1.y);
        d[3] = __floats2half2_rn(u1.z, u1.w);
    }
    if (tid < 128) {
        bbs[tid] = b_bil[tid]; lgs[tid] = ln_g[tid]; lbs[tid] = ln_b[tid];
        b1s[tid] = b1[tid];    w2s[tid] = w2[tid];
    }
    const float b2v = b2[0];
    const float* xb = x + (size_t)b * LL * DD;
    float* Crow = g_C + (size_t)bi * LL;
    __syncthreads();

    #pragma unroll 1
    for (int t = 0; t < 4; ++t) {
        const int j0 = t * 128;

        // ---- Load x_j tile (fp16, zero-pad) ----
        #pragma unroll
        for (int s = 0; s < 8; ++s) {
            int v = tid + (s << 8);
            int row = v >> 4, seg = (v & 15) << 3;
            int j = j0 + row;
            __half2* d = (__half2*)((char*)Xs + row * 272 + seg * 2);
            if (j < LL) {
                const float* sp = &xb[(size_t)j * DD + seg];
                float4 u0 = *(const float4*)sp;
                float4 u1 = *(const float4*)(sp + 4);
                d[0] = __floats2half2_rn(u0.x, u0.y);
                d[1] = __floats2half2_rn(u0.z, u0.w);
                d[2] = __floats2half2_rn(u1.x, u1.y);
                d[3] = __floats2half2_rn(u1.z, u1.w);
            } else {
                __half2 z = __floats2half2_rn(0.f, 0.f);
                d[0] = z; d[1] = z; d[2] = z; d[3] = z;
            }
        }
        __syncthreads();

        // ---- Phase A: pair = X @ Ts^T ----
        float acc[2][8][4];
        #pragma unroll
        for (int mf = 0; mf < 2; ++mf)
            #pragma unroll
            for (int nt = 0; nt < 8; ++nt)
                #pragma unroll
                for (int u = 0; u < 4; ++u) acc[mf][nt][u] = 0.0f;

        #pragma unroll
        for (int kc = 0; kc < 8; ++kc) {
            int o = kc * 8;
            uint32_t a[2][4];
            #pragma unroll
            for (int mf = 0; mf < 2; ++mf) {
                const __half2* Ar = &Xs[(arow + mf * 16 + g) * HP + o];
                a[mf][0] = ldu32(Ar + c);
                a[mf][1] = ldu32(Ar + 8 * HP + c);
                a[mf][2] = ldu32(Ar + c + 4);
                a[mf][3] = ldu32(Ar + 8 * HP + c + 4);
            }
            #pragma unroll
            for (int nt = 0; nt < 8; ++nt) {
                const __half2* Br = &Ts[(bcol + nt * 8 + g) * HP + o];
                uint32_t b0 = ldu32(Br + c);
                uint32_t b1r = ldu32(Br + c + 4);
                mma_f16(acc[0][nt], a[0][0], a[0][1], a[0][2], a[0][3], b0, b1r);
                mma_f16(acc[1][nt], a[1][0], a[1][1], a[1][2], a[1][3], b0, b1r);
            }
        }

        // ---- LN stats (rows: lr = mf*2 + half8) ----
        float s1[4] = {0.f, 0.f, 0.f, 0.f}, s2[4] = {0.f, 0.f, 0.f, 0.f};
        #pragma unroll
        for (int mf = 0; mf < 2; ++mf)
            #pragma unroll
            for (int nt = 0; nt < 8; ++nt) {
                int col = bcol + nt * 8 + 2 * c;
                float bb0 = bbs[col], bb1 = bbs[col + 1];
                acc[mf][nt][0] += bb0; acc[mf][nt][1] += bb1;
                acc[mf][nt][2] += bb0; acc[mf][nt][3] += bb1;
                s1[mf * 2]     += acc[mf][nt][0] + acc[mf][nt][1];
                s2[mf * 2]     += acc[mf][nt][0] * acc[mf][nt][0] + acc[mf][nt][1] * acc[mf][nt][1];
                s1[mf * 2 + 1] += acc[mf][nt][2] + acc[mf][nt][3];
                s2[mf * 2 + 1] += acc[mf][nt][2] * acc[mf][nt][2] + acc[mf][nt][3] * acc[mf][nt][3];
            }
        #pragma unroll
        for (int off = 1; off <= 2; off <<= 1)
            #pragma unroll
            for (int lr = 0; lr < 4; ++lr) {
                s1[lr] += __shfl_xor_sync(0xffffffffu, s1[lr], off);
                s2[lr] += __shfl_xor_sync(0xffffffffu, s2[lr], off);
            }
        if (c == 0) {
            #pragma unroll
            for (int lr = 0; lr < 4; ++lr) {
                int row = arow + (lr >> 1) * 16 + (lr & 1) * 8 + g;
                redA[row * 2 + wk] = make_float2(s1[lr], s2[lr]);
            }
        }
        __syncthreads();

        float mu[4], rs[4];
        #pragma unroll
        for (int lr = 0; lr < 4; ++lr) {
            int row = arow + (lr >> 1) * 16 + (lr & 1) * 8 + g;
            float2 rA = redA[row * 2 + 0], rB = redA[row * 2 + 1];
            float S1 = rA.x + rB.x, S2 = rA.y + rB.y;
            mu[lr] = S1 * (1.0f / 128.0f);
            rs[lr] = rsqrtf(S2 * (1.0f / 128.0f) - mu[lr] * mu[lr] + 1e-5f);
        }

        // ---- Write H (fp16 half2) into Xs ----
        #pragma unroll
        for (int mf = 0; mf < 2; ++mf)
            #pragma unroll
            for (int nt = 0; nt < 8; ++nt) {
                int col = bcol + nt * 8 + 2 * c;
                int h2i = (col >> 1);                 // half2 index within row
                float lg0 = lgs[col], lg1 = lgs[col + 1];
                float lb0 = lbs[col], lb1 = lbs[col + 1];
                int lr0 = mf * 2, lr1 = mf * 2 + 1;
                int r0 = arow + mf * 16 + g;
                Xs[r0 * HP + h2i] = __floats2half2_rn(
                    (acc[mf][nt][0] - mu[lr0]) * rs[lr0] * lg0 + lb0,
                    (acc[mf][nt][1] - mu[lr0]) * rs[lr0] * lg1 + lb1);
                Xs[(r0 + 8) * HP + h2i] = __floats2half2_rn(
                    (acc[mf][nt][2] - mu[lr1]) * rs[lr1] * lg0 + lb0,
                    (acc[mf][nt][3] - mu[lr1]) * rs[lr1] * lg1 + lb1);
            }
        __syncthreads();

        // ---- Phase B: o = H @ W1^T ----
        #pragma unroll
        for (int mf = 0; mf < 2; ++mf)
            #pragma unroll
            for (int nt = 0; nt < 8; ++nt)
                #pragma unroll
                for (int u = 0; u < 4; ++u) acc[mf][nt][u] = 0.0f;

        #pragma unroll
        for (int kc = 0; kc < 8; ++kc) {
            int o = kc * 8;
            uint32_t a[2][4];
            #pragma unroll
            for (int mf = 0; mf < 2; ++mf) {
                const __half2* Ar = &Xs[(arow + mf * 16 + g) * HP + o];
                a[mf][0] = ldu32(Ar + c);
                a[mf][1] = ldu32(Ar + 8 * HP + c);
                a[mf][2] = ldu32(Ar + c + 4);
                a[mf][3] = ldu32(Ar + 8 * HP + c + 4);
            }
            #pragma unroll
            for (int nt = 0; nt < 8; ++nt) {
                const __half2* Br = &W1s[(bcol + nt * 8 + g) * HP + o];
                uint32_t b0 = ldu32(Br + c);
                uint32_t b1r = ldu32(Br + c + 4);
                mma_f16(acc[0][nt], a[0][0], a[0][1], a[0][2], a[0][3], b0, b1r);
                mma_f16(acc[1][nt], a[1][0], a[1][1], a[1][2], a[1][3], b0, b1r);
            }
        }

        // ---- Epilogue: bias, exact GELU, dot w2 ----
        float tsum[4] = {0.f, 0.f, 0.f, 0.f};
        #pragma unroll
        for (int mf = 0; mf < 2; ++mf)
            #pragma unroll
            for (int nt = 0; nt < 8; ++nt) {
                int col = bcol + nt * 8 + 2 * c;
                float c0 = b1s[col], c1 = b1s[col + 1];
                float w0 = w2s[col], w1 = w2s[col + 1];
                float v0 = acc[mf][nt][0] + c0, v1 = acc[mf][nt][1] + c1;
                float v2 = acc[mf][nt][2] + c0, v3 = acc[mf][nt][3] + c1;
                tsum[mf * 2]     += 0.5f * v0 * (1.0f + erff(v0 * 0.70710678118654752f)) * w0
                                  + 0.5f * v1 * (1.0f + erff(v1 * 0.70710678118654752f)) * w1;
                tsum[mf * 2 + 1] += 0.5f * v2 * (1.0f + erff(v2 * 0.70710678118654752f)) * w0
                                  + 0.5f * v3 * (1.0f + erff(v3 * 0.70710678118654752f)) * w1;
            }
        #pragma unroll
        for (int off = 1; off <= 2; off <<= 1)
            #pragma unroll
            for (int lr = 0; lr < 4; ++lr)
                tsum[lr] += __shfl_xor_sync(0xffffffffu, tsum[lr], off);
        if (c == 0) {
            #pragma unroll
            for (int lr = 0; lr < 4; ++lr) {
                int row = arow + (lr >> 1) * 16 + (lr & 1) * 8 + g;
                redB[row * 2 + wk] = tsum[lr];
            }
        }
        __syncthreads();

        if (tid < 128) {
            int j = j0 + tid;
            if (j < LL) Crow[j] = redB[tid * 2] + redB[tid * 2 + 1] + b2v;
        }
        __syncthreads();
    }
}

// ---------------------------------------------------------------------------
// Kernel 3: out[b,i,j] = 0.5 * (C[b,i,j] + C[b,j,i])
// ---------------------------------------------------------------------------
__global__ void k3_sym(float* __restrict__ out)
{
    int idx = blockIdx.x * 256 + threadIdx.x;
    if (idx >= BB * LL * LL) return;
    int b  = idx / (LL * LL);
    int rm = idx - b * LL * LL;
    int i  = rm / LL, j = rm % LL;
    out[idx] = 0.5f * (g_C[idx] + g_C[((size_t)b * LL + j) * LL + i]);
}

// ---------------------------------------------------------------------------
extern "C" void kernel_launch(void* const* d_in, const int* in_sizes, int n_in,
                              void* d_out, int out_size)
{
    (void)in_sizes; (void)n_in; (void)out_size;
    const float* x     = (const float*)d_in[0];
    const float* W_bil = (const float*)d_in[1];
    const float* b_bil = (const float*)d_in[2];
    const float* ln_g  = (const float*)d_in[3];
    const float* ln_b  = (const float*)d_in[4];
    const float* W1    = (const float*)d_in[5];
    const float* b1    = (const float*)d_in[6];
    const float* w2    = (const float*)d_in[7];
    const float* b2    = (const float*)d_in[8];
    float* out = (float*)d_out;

    cudaFuncSetAttribute(k1_tmp,   cudaFuncAttributeMaxDynamicSharedMemorySize, K1_SMEM);
    cudaFuncSetAttribute(k2_fused, cudaFuncAttributeMaxDynamicSharedMemorySize, K2_SMEM);

    dim3 g1(128, (NBI + 127) / 128);   // 128 x 7
    k1_tmp<<<g1, 256, K1_SMEM>>>(x, W_bil);
    k2_fused<<<NBI, 256, K2_SMEM>>>(x, b_bil, ln_g, ln_b, W1, b1, w2, b2);

    int tot = BB * LL * LL;
    k3_sym<<<(tot + 255) / 256, 256>>>(out);
}

// round 7
// speedup vs baseline: 1.9139x; 1.0673x over previous
#include <cuda_runtime.h>
#include <cuda_fp16.h>
#include <math.h>
#include <stdint.h>

#define BB 2
#define LL 401
#define DD 128
#define NBI (BB*LL)   // 802
#define HP 68         // smem row pitch in half2 (136 halfs, 272 B)

__device__ __half g_tmp_h[(size_t)NBI * DD * DD];            // 26.3 MB tmp[b,i,k,e] fp16
__device__ __align__(16) __half2 g_WbT[(size_t)DD * DD * 64]; // 4 MB: [k][e][d-pairs]
__device__ float  g_C[(size_t)BB * LL * LL];

// ---------------------------------------------------------------------------
__device__ __forceinline__ void mma_f16(float c[4],
                                        uint32_t a0, uint32_t a1, uint32_t a2, uint32_t a3,
                                        uint32_t b0, uint32_t b1)
{
    asm volatile(
        "mma.sync.aligned.m16n8k16.row.col.f32.f16.f16.f32 "
        "{%0,%1,%2,%3}, {%4,%5,%6,%7}, {%8,%9}, {%0,%1,%2,%3};"
        : "+f"(c[0]), "+f"(c[1]), "+f"(c[2]), "+f"(c[3])
        : "r"(a0), "r"(a1), "r"(a2), "r"(a3), "r"(b0), "r"(b1));
}
__device__ __forceinline__ uint32_t ldu32(const __half2* p) {
    return *(const uint32_t*)p;
}

// ---------------------------------------------------------------------------
// Kernel 0: one-time transpose W_bil[k][d][e] (fp32) -> g_WbT[k][e][d-pairs] (fp16)
// ---------------------------------------------------------------------------
__global__ __launch_bounds__(256, 2) void k0_transpose(const float* __restrict__ Wb)
{
    __shared__ __half Sg[128 * 130];       // pitch 130 halfs
    const int k   = blockIdx.x;
    const int tid = threadIdx.x;
    const float* Wk = Wb + (size_t)k * DD * DD;

    #pragma unroll
    for (int s = 0; s < 16; ++s) {
        int v = tid + (s << 8);            // float4 units, 4096
        int d = v >> 5, e4 = (v & 31) << 2;
        float4 w = *(const float4*)&Wk[d * DD + e4];
        __half2* dst = (__half2*)&Sg[d * 130 + e4];
        dst[0] = __floats2half2_rn(w.x, w.y);
        dst[1] = __floats2half2_rn(w.z, w.w);
    }
    __syncthreads();

    __half2* out = g_WbT + (size_t)k * (DD * 64);
    #pragma unroll
    for (int s = 0; s < 32; ++s) {
        int v = tid + (s << 8);            // half2 outputs, 8192
        int e = v >> 6, d2 = v & 63;
        __half lo = Sg[(2 * d2) * 130 + e];
        __half hi = Sg[(2 * d2 + 1) * 130 + e];
        out[e * 64 + d2] = __halves2half2(lo, hi);
    }
}

// ---------------------------------------------------------------------------
// Kernel 1 (fp16 mma): tmp[bi][k][e] = sum_d x[bi][d] * W_bil[k][d][e]
// Wt preloaded from g_WbT (coalesced copy). Warps 4(wj) x 2(wk), 32m x 64n.
// ---------------------------------------------------------------------------
#define K1_XS 0u
#define K1_WT 34816u
#define K1_SMEM 69632u

__global__ __launch_bounds__(256, 2) void k1_tmp(const float* __restrict__ x)
{
    extern __shared__ char smc[];
    __half2* Xs = (__half2*)(smc + K1_XS);   // [128][HP] bi rows, d packed
    __half2* Wt = (__half2*)(smc + K1_WT);   // [128][HP] e rows, d packed

    const int k   = blockIdx.x;
    const int bi0 = blockIdx.y * 128;
    const int tid = threadIdx.x, tx = tid & 31, wid = tid >> 5;
    const int wj  = wid & 3, wk = wid >> 2;
    const int g   = tx >> 2, c = tx & 3;
    const int arow = wj * 32, bcol = wk * 64;

    // ---- Wt: coalesced uint4 copy of pre-transposed slice ----
    const __half2* Wsrc = g_WbT + (size_t)k * (DD * 64);
    #pragma unroll
    for (int s = 0; s < 8; ++s) {
        int v = tid + (s << 8);              // uint4 units, 2048
        int row = v >> 4, u = (v & 15) << 2; // half2 offset within row
        uint4 t = *(const uint4*)&Wsrc[row * 64 + u];
        *(uint4*)&Wt[row * HP + u] = t;
    }
    // ---- x rows -> Xs (half2 along d) ----
    #pragma unroll
    for (int s = 0; s < 16; ++s) {
        int v = tid + (s << 8);
        int row = v >> 5, d4 = (v & 31) << 2;
        int bi = bi0 + row;
        __half2 h0, h1;
        if (bi < NBI) {
            float4 t = *(const float4*)&x[(size_t)bi * DD + d4];
            h0 = __floats2half2_rn(t.x, t.y);
            h1 = __floats2half2_rn(t.z, t.w);
        } else {
            h0 = __floats2half2_rn(0.f, 0.f); h1 = h0;
        }
        Xs[row * HP + (d4 >> 1)]     = h0;
        Xs[row * HP + (d4 >> 1) + 1] = h1;
    }
    __syncthreads();

    float acc[2][8][4];
    #pragma unroll
    for (int mf = 0; mf < 2; ++mf)
        #pragma unroll
        for (int nt = 0; nt < 8; ++nt)
            #pragma unroll
            for (int u = 0; u < 4; ++u) acc[mf][nt][u] = 0.0f;

    #pragma unroll
    for (int kc = 0; kc < 8; ++kc) {
        int o = kc * 8;
        uint32_t a[2][4];
        #pragma unroll
        for (int mf = 0; mf < 2; ++mf) {
            const __half2* Ar = &Xs[(arow + mf * 16 + g) * HP + o];
            a[mf][0] = ldu32(Ar + c);
            a[mf][1] = ldu32(Ar + 8 * HP + c);
            a[mf][2] = ldu32(Ar + c + 4);
            a[mf][3] = ldu32(Ar + 8 * HP + c + 4);
        }
        #pragma unroll
        for (int nt = 0; nt < 8; ++nt) {
            const __half2* Br = &Wt[(bcol + nt * 8 + g) * HP + o];
            uint32_t b0 = ldu32(Br + c);
            uint32_t b1 = ldu32(Br + c + 4);
            mma_f16(acc[0][nt], a[0][0], a[0][1], a[0][2], a[0][3], b0, b1);
            mma_f16(acc[1][nt], a[1][0], a[1][1], a[1][2], a[1][3], b0, b1);
        }
    }

    #pragma unroll
    for (int mf = 0; mf < 2; ++mf)
        #pragma unroll
        for (int nt = 0; nt < 8; ++nt) {
            int r0  = bi0 + arow + mf * 16 + g;
            int col = bcol + nt * 8 + 2 * c;
            if (r0 < NBI)
                *(__half2*)&g_tmp_h[(size_t)r0 * (DD * DD) + k * DD + col] =
                    __floats2half2_rn(acc[mf][nt][0], acc[mf][nt][1]);
            int r1 = r0 + 8;
            if (r1 < NBI)
                *(__half2*)&g_tmp_h[(size_t)r1 * (DD * DD) + k * DD + col] =
                    __floats2half2_rn(acc[mf][nt][2], acc[mf][nt][3]);
        }
}

// ---------------------------------------------------------------------------
// Kernel 2 (fp16 mma): per (b,i) CTA, fused, j-tiles {128,128,128,32-active}.
// ---------------------------------------------------------------------------
#define K2_TS 0u
#define K2_WS 34816u
#define K2_XS 69632u
#define K2_CV 104448u
#define K2_RA 107008u
#define K2_RB 109056u
#define K2_SMEM 110080u

__global__ __launch_bounds__(256, 2) void k2_fused(
    const float* __restrict__ x,    const float* __restrict__ b_bil,
    const float* __restrict__ ln_g, const float* __restrict__ ln_b,
    const float* __restrict__ W1,   const float* __restrict__ b1,
    const float* __restrict__ w2,   const float* __restrict__ b2)
{
    extern __shared__ char smc[];
    __half2* Ts  = (__half2*)(smc + K2_TS);
    __half2* W1s = (__half2*)(smc + K2_WS);
    __half2* Xs  = (__half2*)(smc + K2_XS);
    float* cv  = (float*)(smc + K2_CV);
    float* bbs = cv;        float* lgs = cv + 128; float* lbs = cv + 256;
    float* b1s = cv + 384;  float* w2s = cv + 512;
    float2* redA = (float2*)(smc + K2_RA);
    float*  redB = (float*) (smc + K2_RB);

    const int bi  = blockIdx.x;
    const int b   = bi / LL;
    const int tid = threadIdx.x, tx = tid & 31, wid = tid >> 5;
    const int wj  = wid & 3, wk = wid >> 2;
    const int g   = tx >> 2, c = tx & 3;
    const int arow = wj * 32, bcol = wk * 64;

    const __half* tp = g_tmp_h + (size_t)bi * DD * DD;
    #pragma unroll
    for (int s = 0; s < 8; ++s) {
        int v = tid + (s << 8);
        int row = v >> 4, seg = (v & 15) << 3;
        uint4 tv = *(const uint4*)&tp[row * DD + seg];
        *(uint4*)((char*)Ts + row * 272 + seg * 2) = tv;
        const float* wp = &W1[row * DD + seg];
        float4 u0 = *(const float4*)wp;
        float4 u1 = *(const float4*)(wp + 4);
        __half2* d = (__half2*)((char*)W1s + row * 272 + seg * 2);
        d[0] = __floats2half2_rn(u0.x, u0.y);
        d[1] = __floats2half2_rn(u0.z, u0.w);
        d[2] = __floats2half2_rn(u1.x, u1.y);
        d[3] = __floats2half2_rn(u1.z, u1.w);
    }
    if (tid < 128) {
        bbs[tid] = b_bil[tid]; lgs[tid] = ln_g[tid]; lbs[tid] = ln_b[tid];
        b1s[tid] = b1[tid];    w2s[tid] = w2[tid];
    }
    const float b2v = b2[0];
    const float* xb = x + (size_t)b * LL * DD;
    float* Crow = g_C + (size_t)bi * LL;
    __syncthreads();

    #pragma unroll 1
    for (int t = 0; t < 4; ++t) {
        const int j0 = t * 128;
        const int mrows = (t == 3) ? 32 : 128;
        const bool active = (arow < mrows);

        // ---- Load x_j tile (fp16, zero-pad) ----
        #pragma unroll
        for (int s = 0; s < 8; ++s) {
            int v = tid + (s << 8);
            int row = v >> 4, seg = (v & 15) << 3;
            int j = j0 + row;
            __half2* d = (__half2*)((char*)Xs + row * 272 + seg * 2);
            if (j < LL) {
                const float* sp = &xb[(size_t)j * DD + seg];
                float4 u0 = *(const float4*)sp;
                float4 u1 = *(const float4*)(sp + 4);
                d[0] = __floats2half2_rn(u0.x, u0.y);
                d[1] = __floats2half2_rn(u0.z, u0.w);
                d[2] = __floats2half2_rn(u1.x, u1.y);
                d[3] = __floats2half2_rn(u1.z, u1.w);
            } else {
                __half2 z = __floats2half2_rn(0.f, 0.f);
                d[0] = z; d[1] = z; d[2] = z; d[3] = z;
            }
        }
        __syncthreads();

        float acc[2][8][4];
        float s1[4], s2[4];
        if (active) {
            // ---- Phase A: pair = X @ Ts^T ----
            #pragma unroll
            for (int mf = 0; mf < 2; ++mf)
                #pragma unroll
                for (int nt = 0; nt < 8; ++nt)
                    #pragma unroll
                    for (int u = 0; u < 4; ++u) acc[mf][nt][u] = 0.0f;

            #pragma unroll
            for (int kc = 0; kc < 8; ++kc) {
                int o = kc * 8;
                uint32_t a[2][4];
                #pragma unroll
                for (int mf = 0; mf < 2; ++mf) {
                    const __half2* Ar = &Xs[(arow + mf * 16 + g) * HP + o];
                    a[mf][0] = ldu32(Ar + c);
                    a[mf][1] = ldu32(Ar + 8 * HP + c);
                    a[mf][2] = ldu32(Ar + c + 4);
                    a[mf][3] = ldu32(Ar + 8 * HP + c + 4);
                }
                #pragma unroll
                for (int nt = 0; nt < 8; ++nt) {
                    const __half2* Br = &Ts[(bcol + nt * 8 + g) * HP + o];
                    uint32_t b0 = ldu32(Br + c);
                    uint32_t b1r = ldu32(Br + c + 4);
                    mma_f16(acc[0][nt], a[0][0], a[0][1], a[0][2], a[0][3], b0, b1r);
                    mma_f16(acc[1][nt], a[1][0], a[1][1], a[1][2], a[1][3], b0, b1r);
                }
            }

            // ---- LN stats ----
            #pragma unroll
            for (int lr = 0; lr < 4; ++lr) { s1[lr] = 0.f; s2[lr] = 0.f; }
            #pragma unroll
            for (int mf = 0; mf < 2; ++mf)
                #pragma unroll
                for (int nt = 0; nt < 8; ++nt) {
                    int col = bcol + nt * 8 + 2 * c;
                    float bb0 = bbs[col], bb1 = bbs[col + 1];
                    acc[mf][nt][0] += bb0; acc[mf][nt][1] += bb1;
                    acc[mf][nt][2] += bb0; acc[mf][nt][3] += bb1;
                    s1[mf * 2]     += acc[mf][nt][0] + acc[mf][nt][1];
                    s2[mf * 2]     += acc[mf][nt][0] * acc[mf][nt][0] + acc[mf][nt][1] * acc[mf][nt][1];
                    s1[mf * 2 + 1] += acc[mf][nt][2] + acc[mf][nt][3];
                    s2[mf * 2 + 1] += acc[mf][nt][2] * acc[mf][nt][2] + acc[mf][nt][3] * acc[mf][nt][3];
                }
            #pragma unroll
            for (int off = 1; off <= 2; off <<= 1)
                #pragma unroll
                for (int lr = 0; lr < 4; ++lr) {
                    s1[lr] += __shfl_xor_sync(0xffffffffu, s1[lr], off);
                    s2[lr] += __shfl_xor_sync(0xffffffffu, s2[lr], off);
                }
            if (c == 0) {
                #pragma unroll
                for (int lr = 0; lr < 4; ++lr) {
                    int row = arow + (lr >> 1) * 16 + (lr & 1) * 8 + g;
                    redA[row * 2 + wk] = make_float2(s1[lr], s2[lr]);
                }
            }
        }
        __syncthreads();

        if (active) {
            float mu[4], rs[4];
            #pragma unroll
            for (int lr = 0; lr < 4; ++lr) {
                int row = arow + (lr >> 1) * 16 + (lr & 1) * 8 + g;
                float2 rA = redA[row * 2 + 0], rB = redA[row * 2 + 1];
                float S1 = rA.x + rB.x, S2 = rA.y + rB.y;
                mu[lr] = S1 * (1.0f / 128.0f);
                rs[lr] = rsqrtf(S2 * (1.0f / 128.0f) - mu[lr] * mu[lr] + 1e-5f);
            }
            // ---- Write H (fp16) into Xs ----
            #pragma unroll
            for (int mf = 0; mf < 2; ++mf)
                #pragma unroll
                for (int nt = 0; nt < 8; ++nt) {
                    int col = bcol + nt * 8 + 2 * c;
                    int h2i = (col >> 1);
                    float lg0 = lgs[col], lg1 = lgs[col + 1];
                    float lb0 = lbs[col], lb1 = lbs[col + 1];
                    int lr0 = mf * 2, lr1 = mf * 2 + 1;
                    int r0 = arow + mf * 16 + g;
                    Xs[r0 * HP + h2i] = __floats2half2_rn(
                        (acc[mf][nt][0] - mu[lr0]) * rs[lr0] * lg0 + lb0,
                        (acc[mf][nt][1] - mu[lr0]) * rs[lr0] * lg1 + lb1);
                    Xs[(r0 + 8) * HP + h2i] = __floats2half2_rn(
                        (acc[mf][nt][2] - mu[lr1]) * rs[lr1] * lg0 + lb0,
                        (acc[mf][nt][3] - mu[lr1]) * rs[lr1] * lg1 + lb1);
                }
        }
        __syncthreads();

        if (active) {
            // ---- Phase B: o = H @ W1^T ----
            #pragma unroll
            for (int mf = 0; mf < 2; ++mf)
                #pragma unroll
                for (int nt = 0; nt < 8; ++nt)
                    #pragma unroll
                    for (int u = 0; u < 4; ++u) acc[mf][nt][u] = 0.0f;

            #pragma unroll
            for (int kc = 0; kc < 8; ++kc) {
                int o = kc * 8;
                uint32_t a[2][4];
                #pragma unroll
                for (int mf = 0; mf < 2; ++mf) {
                    const __half2* Ar = &Xs[(arow + mf * 16 + g) * HP + o];
                    a[mf][0] = ldu32(Ar + c);
                    a[mf][1] = ldu32(Ar + 8 * HP + c);
                    a[mf][2] = ldu32(Ar + c + 4);
                    a[mf][3] = ldu32(Ar + 8 * HP + c + 4);
                }
                #pragma unroll
                for (int nt = 0; nt < 8; ++nt) {
                    const __half2* Br = &W1s[(bcol + nt * 8 + g) * HP + o];
                    uint32_t b0 = ldu32(Br + c);
                    uint32_t b1r = ldu32(Br + c + 4);
                    mma_f16(acc[0][nt], a[0][0], a[0][1], a[0][2], a[0][3], b0, b1r);
                    mma_f16(acc[1][nt], a[1][0], a[1][1], a[1][2], a[1][3], b0, b1r);
                }
            }

            // ---- Epilogue ----
            float tsum[4] = {0.f, 0.f, 0.f, 0.f};
            #pragma unroll
            for (int mf = 0; mf < 2; ++mf)
                #pragma unroll
                for (int nt = 0; nt < 8; ++nt) {
                    int col = bcol + nt * 8 + 2 * c;
                    float c0 = b1s[col], c1 = b1s[col + 1];
                    float w0 = w2s[col], w1 = w2s[col + 1];
                    float v0 = acc[mf][nt][0] + c0, v1 = acc[mf][nt][1] + c1;
                    float v2 = acc[mf][nt][2] + c0, v3 = acc[mf][nt][3] + c1;
                    tsum[mf * 2]     += 0.5f * v0 * (1.0f + erff(v0 * 0.70710678118654752f)) * w0
                                      + 0.5f * v1 * (1.0f + erff(v1 * 0.70710678118654752f)) * w1;
                    tsum[mf * 2 + 1] += 0.5f * v2 * (1.0f + erff(v2 * 0.70710678118654752f)) * w0
                                      + 0.5f * v3 * (1.0f + erff(v3 * 0.70710678118654752f)) * w1;
                }
            #pragma unroll
            for (int off = 1; off <= 2; off <<= 1)
                #pragma unroll
                for (int lr = 0; lr < 4; ++lr)
                    tsum[lr] += __shfl_xor_sync(0xffffffffu, tsum[lr], off);
            if (c == 0) {
                #pragma unroll
                for (int lr = 0; lr < 4; ++lr) {
                    int row = arow + (lr >> 1) * 16 + (lr & 1) * 8 + g;
                    redB[row * 2 + wk] = tsum[lr];
                }
            }
        }
        __syncthreads();

        if (tid < mrows) {
            int j = j0 + tid;
            if (j < LL) Crow[j] = redB[tid * 2] + redB[tid * 2 + 1] + b2v;
        }
        __syncthreads();
    }
}

// ---------------------------------------------------------------------------
__global__ void k3_sym(float* __restrict__ out)
{
    int idx = blockIdx.x * 256 + threadIdx.x;
    if (idx >= BB * LL * LL) return;
    int b  = idx / (LL * LL);
    int rm = idx - b * LL * LL;
    int i  = rm / LL, j = rm % LL;
    out[idx] = 0.5f * (g_C[idx] + g_C[((size_t)b * LL + j) * LL + i]);
}

// ---------------------------------------------------------------------------
extern "C" void kernel_launch(void* const* d_in, const int* in_sizes, int n_in,
                              void* d_out, int out_size)
{
    (void)in_sizes; (void)n_in; (void)out_size;
    const float* x     = (const float*)d_in[0];
    const float* W_bil = (const float*)d_in[1];
    const float* b_bil = (const float*)d_in[2];
    const float* ln_g  = (const float*)d_in[3];
    const float* ln_b  = (const float*)d_in[4];
    const float* W1    = (const float*)d_in[5];
    const float* b1    = (const float*)d_in[6];
    const float* w2    = (const float*)d_in[7];
    const float* b2    = (const float*)d_in[8];
    float* out = (float*)d_out;

    cudaFuncSetAttribute(k1_tmp,   cudaFuncAttributeMaxDynamicSharedMemorySize, K1_SMEM);
    cudaFuncSetAttribute(k2_fused, cudaFuncAttributeMaxDynamicSharedMemorySize, K2_SMEM);

    k0_transpose<<<128, 256>>>(W_bil);
    dim3 g1(128, (NBI + 127) / 128);   // 128 x 7
    k1_tmp<<<g1, 256, K1_SMEM>>>(x);
    k2_fused<<<NBI, 256, K2_SMEM>>>(x, b_bil, ln_g, ln_b, W1, b1, w2, b2);

    int tot = BB * LL * LL;
    k3_sym<<<(tot + 255) / 256, 256>>>(out);
}

// round 8
// speedup vs baseline: 1.9466x; 1.0171x over previous
#include <cuda_runtime.h>
#include <cuda_fp16.h>
#include <math.h>
#include <stdint.h>

#define BB 2
#define LL 401
#define DD 128
#define NBI (BB*LL)   // 802
#define HP 68         // smem row pitch in half2 (136 halfs, 272 B)

__device__ __half g_tmp_h[(size_t)NBI * DD * DD];             // 26.3 MB tmp[b,i,k,e] fp16
__device__ __align__(16) __half2 g_WbT[(size_t)DD * DD * 64]; // 4 MB: [k][e][d-pairs]
__device__ float  g_C[(size_t)BB * LL * LL];

// ---------------------------------------------------------------------------
__device__ __forceinline__ void mma_f16(float c[4],
                                        uint32_t a0, uint32_t a1, uint32_t a2, uint32_t a3,
                                        uint32_t b0, uint32_t b1)
{
    asm volatile(
        "mma.sync.aligned.m16n8k16.row.col.f32.f16.f16.f32 "
        "{%0,%1,%2,%3}, {%4,%5,%6,%7}, {%8,%9}, {%0,%1,%2,%3};"
        : "+f"(c[0]), "+f"(c[1]), "+f"(c[2]), "+f"(c[3])
        : "r"(a0), "r"(a1), "r"(a2), "r"(a3), "r"(b0), "r"(b1));
}
__device__ __forceinline__ void ldsm4(uint32_t r[4], uint32_t addr)
{
    asm volatile("ldmatrix.sync.aligned.m8n8.x4.shared.b16 {%0,%1,%2,%3}, [%4];"
                 : "=r"(r[0]), "=r"(r[1]), "=r"(r[2]), "=r"(r[3]) : "r"(addr));
}

// ---------------------------------------------------------------------------
// Kernel 0: one-time transpose W_bil[k][d][e] (fp32) -> g_WbT[k][e][d-pairs] (fp16)
// ---------------------------------------------------------------------------
__global__ __launch_bounds__(256, 2) void k0_transpose(const float* __restrict__ Wb)
{
    __shared__ __half Sg[128 * 130];
    const int k   = blockIdx.x;
    const int tid = threadIdx.x;
    const float* Wk = Wb + (size_t)k * DD * DD;

    #pragma unroll
    for (int s = 0; s < 16; ++s) {
        int v = tid + (s << 8);
        int d = v >> 5, e4 = (v & 31) << 2;
        float4 w = *(const float4*)&Wk[d * DD + e4];
        __half2* dst = (__half2*)&Sg[d * 130 + e4];
        dst[0] = __floats2half2_rn(w.x, w.y);
        dst[1] = __floats2half2_rn(w.z, w.w);
    }
    __syncthreads();

    __half2* out = g_WbT + (size_t)k * (DD * 64);
    #pragma unroll
    for (int s = 0; s < 32; ++s) {
        int v = tid + (s << 8);
        int e = v >> 6, d2 = v & 63;
        __half lo = Sg[(2 * d2) * 130 + e];
        __half hi = Sg[(2 * d2 + 1) * 130 + e];
        out[e * 64 + d2] = __halves2half2(lo, hi);
    }
}

// ---------------------------------------------------------------------------
// Kernel 1 (fp16 mma + ldmatrix): tmp[bi][k][e] = sum_d x[bi][d]*W_bil[k][d][e]
// ---------------------------------------------------------------------------
#define K1_XS 0u
#define K1_WT 34816u
#define K1_SMEM 69632u

__global__ __launch_bounds__(256, 2) void k1_tmp(const float* __restrict__ x)
{
    extern __shared__ char smc[];
    __half2* Xs = (__half2*)(smc + K1_XS);   // [128][HP] bi rows, d packed
    __half2* Wt = (__half2*)(smc + K1_WT);   // [128][HP] e rows, d packed

    const int k   = blockIdx.x;
    const int bi0 = blockIdx.y * 128;
    const int tid = threadIdx.x, tx = tid & 31, wid = tid >> 5;
    const int wj  = wid & 3, wk = wid >> 2;
    const int g   = tx >> 2, c = tx & 3;
    const int arow = wj * 32, bcol = wk * 64;

    const __half2* Wsrc = g_WbT + (size_t)k * (DD * 64);
    #pragma unroll
    for (int s = 0; s < 8; ++s) {
        int v = tid + (s << 8);
        int row = v >> 4, u = (v & 15) << 2;
        uint4 t = *(const uint4*)&Wsrc[row * 64 + u];
        *(uint4*)&Wt[row * HP + u] = t;
    }
    #pragma unroll
    for (int s = 0; s < 16; ++s) {
        int v = tid + (s << 8);
        int row = v >> 5, d4 = (v & 31) << 2;
        int bi = bi0 + row;
        __half2 h0, h1;
        if (bi < NBI) {
            float4 t = *(const float4*)&x[(size_t)bi * DD + d4];
            h0 = __floats2half2_rn(t.x, t.y);
            h1 = __floats2half2_rn(t.z, t.w);
        } else {
            h0 = __floats2half2_rn(0.f, 0.f); h1 = h0;
        }
        Xs[row * HP + (d4 >> 1)]     = h0;
        Xs[row * HP + (d4 >> 1) + 1] = h1;
    }
    __syncthreads();

    const uint32_t sb  = (uint32_t)__cvta_generic_to_shared(smc);
    const uint32_t sbX = sb + K1_XS, sbW = sb + K1_WT;

    uint32_t aAddr[2], bOff[4];
    #pragma unroll
    for (int mf = 0; mf < 2; ++mf) {
        int row = arow + mf * 16 + (tx & 7) + ((tx & 8) ? 8 : 0);
        aAddr[mf] = sbX + row * 272 + ((tx & 16) ? 16 : 0);
    }
    #pragma unroll
    for (int p = 0; p < 4; ++p) {
        int row = bcol + p * 16 + (tx & 7) + ((tx & 16) ? 8 : 0);
        bOff[p] = row * 272 + ((tx & 8) ? 16 : 0);
    }

    float acc[2][8][4];
    #pragma unroll
    for (int mf = 0; mf < 2; ++mf)
        #pragma unroll
        for (int nt = 0; nt < 8; ++nt)
            #pragma unroll
            for (int u = 0; u < 4; ++u) acc[mf][nt][u] = 0.0f;

    #pragma unroll
    for (int kc = 0; kc < 8; ++kc) {
        int ko = kc * 32;
        uint32_t a0[4], a1[4];
        ldsm4(a0, aAddr[0] + ko);
        ldsm4(a1, aAddr[1] + ko);
        #pragma unroll
        for (int p = 0; p < 4; ++p) {
            uint32_t bb[4];
            ldsm4(bb, sbW + bOff[p] + ko);
            mma_f16(acc[0][2 * p],     a0[0], a0[1], a0[2], a0[3], bb[0], bb[1]);
            mma_f16(acc[1][2 * p],     a1[0], a1[1], a1[2], a1[3], bb[0], bb[1]);
            mma_f16(acc[0][2 * p + 1], a0[0], a0[1], a0[2], a0[3], bb[2], bb[3]);
            mma_f16(acc[1][2 * p + 1], a1[0], a1[1], a1[2], a1[3], bb[2], bb[3]);
        }
    }

    #pragma unroll
    for (int mf = 0; mf < 2; ++mf)
        #pragma unroll
        for (int nt = 0; nt < 8; ++nt) {
            int r0  = bi0 + arow + mf * 16 + g;
            int col = bcol + nt * 8 + 2 * c;
            if (r0 < NBI)
                *(__half2*)&g_tmp_h[(size_t)r0 * (DD * DD) + k * DD + col] =
                    __floats2half2_rn(acc[mf][nt][0], acc[mf][nt][1]);
            int r1 = r0 + 8;
            if (r1 < NBI)
                *(__half2*)&g_tmp_h[(size_t)r1 * (DD * DD) + k * DD + col] =
                    __floats2half2_rn(acc[mf][nt][2], acc[mf][nt][3]);
        }
}

// ---------------------------------------------------------------------------
// Kernel 2 (fp16 mma + ldmatrix): per (b,i) CTA, fused, tiles {128,128,128,32}.
// ---------------------------------------------------------------------------
#define K2_TS 0u
#define K2_WS 34816u
#define K2_XS 69632u
#define K2_CV 104448u
#define K2_RA 107008u
#define K2_RB 109056u
#define K2_SMEM 110080u

__global__ __launch_bounds__(256, 2) void k2_fused(
    const float* __restrict__ x,    const float* __restrict__ b_bil,
    const float* __restrict__ ln_g, const float* __restrict__ ln_b,
    const float* __restrict__ W1,   const float* __restrict__ b1,
    const float* __restrict__ w2,   const float* __restrict__ b2)
{
    extern __shared__ char smc[];
    __half2* Ts  = (__half2*)(smc + K2_TS);
    __half2* W1s = (__half2*)(smc + K2_WS);
    __half2* Xs  = (__half2*)(smc + K2_XS);
    float* cv  = (float*)(smc + K2_CV);
    float* bbs = cv;        float* lgs = cv + 128; float* lbs = cv + 256;
    float* b1s = cv + 384;  float* w2s = cv + 512;
    float2* redA = (float2*)(smc + K2_RA);
    float*  redB = (float*) (smc + K2_RB);

    const int bi  = blockIdx.x;
    const int b   = bi / LL;
    const int tid = threadIdx.x, tx = tid & 31, wid = tid >> 5;
    const int wj  = wid & 3, wk = wid >> 2;
    const int g   = tx >> 2, c = tx & 3;
    const int arow = wj * 32, bcol = wk * 64;

    const __half* tp = g_tmp_h + (size_t)bi * DD * DD;
    #pragma unroll
    for (int s = 0; s < 8; ++s) {
        int v = tid + (s << 8);
        int row = v >> 4, seg = (v & 15) << 3;
        uint4 tv = *(const uint4*)&tp[row * DD + seg];
        *(uint4*)((char*)Ts + row * 272 + seg * 2) = tv;
        const float* wp = &W1[row * DD + seg];
        float4 u0 = *(const float4*)wp;
        float4 u1 = *(const float4*)(wp + 4);
        __half2* d = (__half2*)((char*)W1s + row * 272 + seg * 2);
        d[0] = __floats2half2_rn(u0.x, u0.y);
        d[1] = __floats2half2_rn(u0.z, u0.w);
        d[2] = __floats2half2_rn(u1.x, u1.y);
        d[3] = __floats2half2_rn(u1.z, u1.w);
    }
    if (tid < 128) {
        bbs[tid] = b_bil[tid]; lgs[tid] = ln_g[tid]; lbs[tid] = ln_b[tid];
        b1s[tid] = b1[tid];    w2s[tid] = w2[tid];
    }
    const float b2v = b2[0];
    const float* xb = x + (size_t)b * LL * DD;
    float* Crow = g_C + (size_t)bi * LL;

    const uint32_t sb  = (uint32_t)__cvta_generic_to_shared(smc);
    const uint32_t sbX = sb + K2_XS, sbT = sb + K2_TS, sbW = sb + K2_WS;

    uint32_t aAddr[2], bOff[4];
    #pragma unroll
    for (int mf = 0; mf < 2; ++mf) {
        int row = arow + mf * 16 + (tx & 7) + ((tx & 8) ? 8 : 0);
        aAddr[mf] = sbX + row * 272 + ((tx & 16) ? 16 : 0);
    }
    #pragma unroll
    for (int p = 0; p < 4; ++p) {
        int row = bcol + p * 16 + (tx & 7) + ((tx & 16) ? 8 : 0);
        bOff[p] = row * 272 + ((tx & 8) ? 16 : 0);
    }
    __syncthreads();

    #pragma unroll 1
    for (int t = 0; t < 4; ++t) {
        const int j0 = t * 128;
        const int mrows = (t == 3) ? 32 : 128;
        const bool active = (arow < mrows);

        // ---- Load x_j tile (fp16, zero-pad) ----
        #pragma unroll
        for (int s = 0; s < 8; ++s) {
            int v = tid + (s << 8);
            int row = v >> 4, seg = (v & 15) << 3;
            int j = j0 + row;
            __half2* d = (__half2*)((char*)Xs + row * 272 + seg * 2);
            if (j < LL) {
                const float* sp = &xb[(size_t)j * DD + seg];
                float4 u0 = *(const float4*)sp;
                float4 u1 = *(const float4*)(sp + 4);
                d[0] = __floats2half2_rn(u0.x, u0.y);
                d[1] = __floats2half2_rn(u0.z, u0.w);
                d[2] = __floats2half2_rn(u1.x, u1.y);
                d[3] = __floats2half2_rn(u1.z, u1.w);
            } else {
                __half2 z = __floats2half2_rn(0.f, 0.f);
                d[0] = z; d[1] = z; d[2] = z; d[3] = z;
            }
        }
        __syncthreads();

        float acc[2][8][4];
        float s1[4], s2[4];
        if (active) {
            // ---- Phase A: pair = X @ Ts^T ----
            #pragma unroll
            for (int mf = 0; mf < 2; ++mf)
                #pragma unroll
                for (int nt = 0; nt < 8; ++nt)
                    #pragma unroll
                    for (int u = 0; u < 4; ++u) acc[mf][nt][u] = 0.0f;

            #pragma unroll
            for (int kc = 0; kc < 8; ++kc) {
                int ko = kc * 32;
                uint32_t a0[4], a1[4];
                ldsm4(a0, aAddr[0] + ko);
                ldsm4(a1, aAddr[1] + ko);
                #pragma unroll
                for (int p = 0; p < 4; ++p) {
                    uint32_t bb[4];
                    ldsm4(bb, sbT + bOff[p] + ko);
                    mma_f16(acc[0][2 * p],     a0[0], a0[1], a0[2], a0[3], bb[0], bb[1]);
                    mma_f16(acc[1][2 * p],     a1[0], a1[1], a1[2], a1[3], bb[0], bb[1]);
                    mma_f16(acc[0][2 * p + 1], a0[0], a0[1], a0[2], a0[3], bb[2], bb[3]);
                    mma_f16(acc[1][2 * p + 1], a1[0], a1[1], a1[2], a1[3], bb[2], bb[3]);
                }
            }

            // ---- LN stats ----
            #pragma unroll
            for (int lr = 0; lr < 4; ++lr) { s1[lr] = 0.f; s2[lr] = 0.f; }
            #pragma unroll
            for (int mf = 0; mf < 2; ++mf)
                #pragma unroll
                for (int nt = 0; nt < 8; ++nt) {
                    int col = bcol + nt * 8 + 2 * c;
                    float bb0 = bbs[col], bb1 = bbs[col + 1];
                    acc[mf][nt][0] += bb0; acc[mf][nt][1] += bb1;
                    acc[mf][nt][2] += bb0; acc[mf][nt][3] += bb1;
                    s1[mf * 2]     += acc[mf][nt][0] + acc[mf][nt][1];
                    s2[mf * 2]     += acc[mf][nt][0] * acc[mf][nt][0] + acc[mf][nt][1] * acc[mf][nt][1];
                    s1[mf * 2 + 1] += acc[mf][nt][2] + acc[mf][nt][3];
                    s2[mf * 2 + 1] += acc[mf][nt][2] * acc[mf][nt][2] + acc[mf][nt][3] * acc[mf][nt][3];
                }
            #pragma unroll
            for (int off = 1; off <= 2; off <<= 1)
                #pragma unroll
                for (int lr = 0; lr < 4; ++lr) {
                    s1[lr] += __shfl_xor_sync(0xffffffffu, s1[lr], off);
                    s2[lr] += __shfl_xor_sync(0xffffffffu, s2[lr], off);
                }
            if (c == 0) {
                #pragma unroll
                for (int lr = 0; lr < 4; ++lr) {
                    int row = arow + (lr >> 1) * 16 + (lr & 1) * 8 + g;
                    redA[row * 2 + wk] = make_float2(s1[lr], s2[lr]);
                }
            }
        }
        __syncthreads();

        if (active) {
            float mu[4], rs[4];
            #pragma unroll
            for (int lr = 0; lr < 4; ++lr) {
                int row = arow + (lr >> 1) * 16 + (lr & 1) * 8 + g;
                float2 rA = redA[row * 2 + 0], rB = redA[row * 2 + 1];
                float S1 = rA.x + rB.x, S2 = rA.y + rB.y;
                mu[lr] = S1 * (1.0f / 128.0f);
                rs[lr] = rsqrtf(S2 * (1.0f / 128.0f) - mu[lr] * mu[lr] + 1e-5f);
            }
            // ---- Write H (fp16) into Xs ----
            #pragma unroll
            for (int mf = 0; mf < 2; ++mf)
                #pragma unroll
                for (int nt = 0; nt < 8; ++nt) {
                    int col = bcol + nt * 8 + 2 * c;
                    int h2i = (col >> 1);
                    float lg0 = lgs[col], lg1 = lgs[col + 1];
                    float lb0 = lbs[col], lb1 = lbs[col + 1];
                    int lr0 = mf * 2, lr1 = mf * 2 + 1;
                    int r0 = arow + mf * 16 + g;
                    Xs[r0 * HP + h2i] = __floats2half2_rn(
                        (acc[mf][nt][0] - mu[lr0]) * rs[lr0] * lg0 + lb0,
                        (acc[mf][nt][1] - mu[lr0]) * rs[lr0] * lg1 + lb1);
                    Xs[(r0 + 8) * HP + h2i] = __floats2half2_rn(
                        (acc[mf][nt][2] - mu[lr1]) * rs[lr1] * lg0 + lb0,
                        (acc[mf][nt][3] - mu[lr1]) * rs[lr1] * lg1 + lb1);
                }
        }
        __syncthreads();

        if (active) {
            // ---- Phase B: o = H @ W1^T ----
            #pragma unroll
            for (int mf = 0; mf < 2; ++mf)
                #pragma unroll
                for (int nt = 0; nt < 8; ++nt)
                    #pragma unroll
                    for (int u = 0; u < 4; ++u) acc[mf][nt][u] = 0.0f;

            #pragma unroll
            for (int kc = 0; kc < 8; ++kc) {
                int ko = kc * 32;
                uint32_t a0[4], a1[4];
                ldsm4(a0, aAddr[0] + ko);
                ldsm4(a1, aAddr[1] + ko);
                #pragma unroll
                for (int p = 0; p < 4; ++p) {
                    uint32_t bb[4];
                    ldsm4(bb, sbW + bOff[p] + ko);
                    mma_f16(acc[0][2 * p],     a0[0], a0[1], a0[2], a0[3], bb[0], bb[1]);
                    mma_f16(acc[1][2 * p],     a1[0], a1[1], a1[2], a1[3], bb[0], bb[1]);
                    mma_f16(acc[0][2 * p + 1], a0[0], a0[1], a0[2], a0[3], bb[2], bb[3]);
                    mma_f16(acc[1][2 * p + 1], a1[0], a1[1], a1[2], a1[3], bb[2], bb[3]);
                }
            }

            // ---- Epilogue ----
            float tsum[4] = {0.f, 0.f, 0.f, 0.f};
            #pragma unroll
            for (int mf = 0; mf < 2; ++mf)
                #pragma unroll
                for (int nt = 0; nt < 8; ++nt) {
                    int col = bcol + nt * 8 + 2 * c;
                    float c0 = b1s[col], c1 = b1s[col + 1];
                    float w0 = w2s[col], w1 = w2s[col + 1];
                    float v0 = acc[mf][nt][0] + c0, v1 = acc[mf][nt][1] + c1;
                    float v2 = acc[mf][nt][2] + c0, v3 = acc[mf][nt][3] + c1;
                    tsum[mf * 2]     += 0.5f * v0 * (1.0f + erff(v0 * 0.70710678118654752f)) * w0
                                      + 0.5f * v1 * (1.0f + erff(v1 * 0.70710678118654752f)) * w1;
                    tsum[mf * 2 + 1] += 0.5f * v2 * (1.0f + erff(v2 * 0.70710678118654752f)) * w0
                                      + 0.5f * v3 * (1.0f + erff(v3 * 0.70710678118654752f)) * w1;
                }
            #pragma unroll
            for (int off = 1; off <= 2; off <<= 1)
                #pragma unroll
                for (int lr = 0; lr < 4; ++lr)
                    tsum[lr] += __shfl_xor_sync(0xffffffffu, tsum[lr], off);
            if (c == 0) {
                #pragma unroll
                for (int lr = 0; lr < 4; ++lr) {
                    int row = arow + (lr >> 1) * 16 + (lr & 1) * 8 + g;
                    redB[row * 2 + wk] = tsum[lr];
                }
            }
        }
        __syncthreads();

        if (tid < mrows) {
            int j = j0 + tid;
            if (j < LL) Crow[j] = redB[tid * 2] + redB[tid * 2 + 1] + b2v;
        }
        // no trailing sync: C-write reads redB only; next tile writes Xs (disjoint)
    }
}

// ---------------------------------------------------------------------------
__global__ void k3_sym(float* __restrict__ out)
{
    int idx = blockIdx.x * 256 + threadIdx.x;
    if (idx >= BB * LL * LL) return;
    int b  = idx / (LL * LL);
    int rm = idx - b * LL * LL;
    int i  = rm / LL, j = rm % LL;
    out[idx] = 0.5f * (g_C[idx] + g_C[((size_t)b * LL + j) * LL + i]);
}

// ---------------------------------------------------------------------------
extern "C" void kernel_launch(void* const* d_in, const int* in_sizes, int n_in,
                              void* d_out, int out_size)
{
    (void)in_sizes; (void)n_in; (void)out_size;
    const float* x     = (const float*)d_in[0];
    const float* W_bil = (const float*)d_in[1];
    const float* b_bil = (const float*)d_in[2];
    const float* ln_g  = (const float*)d_in[3];
    const float* ln_b  = (const float*)d_in[4];
    const float* W1    = (const float*)d_in[5];
    const float* b1    = (const float*)d_in[6];
    const float* w2    = (const float*)d_in[7];
    const float* b2    = (const float*)d_in[8];
    float* out = (float*)d_out;

    cudaFuncSetAttribute(k1_tmp,   cudaFuncAttributeMaxDynamicSharedMemorySize, K1_SMEM);
    cudaFuncSetAttribute(k2_fused, cudaFuncAttributeMaxDynamicSharedMemorySize, K2_SMEM);

    k0_transpose<<<128, 256>>>(W_bil);
    dim3 g1(128, (NBI + 127) / 128);   // 128 x 7
    k1_tmp<<<g1, 256, K1_SMEM>>>(x);
    k2_fused<<<NBI, 256, K2_SMEM>>>(x, b_bil, ln_g, ln_b, W1, b1, w2, b2);

    int tot = BB * LL * LL;
    k3_sym<<<(tot + 255) / 256, 256>>>(out);
}

// round 9
// speedup vs baseline: 1.9798x; 1.0170x over previous
#include <cuda_runtime.h>
#include <cuda_fp16.h>
#include <math.h>
#include <stdint.h>

#define BB 2
#define LL 401
#define DD 128
#define NBI (BB*LL)   // 802
#define HP 68         // smem row pitch in half2 (136 halfs, 272 B)

__device__ __half g_tmp_h[(size_t)NBI * DD * DD];             // 26.3 MB tmp[b,i,k,e] fp16
__device__ __align__(16) __half2 g_WbT[(size_t)DD * DD * 64]; // 4 MB: [k][e][d-pairs]
__device__ float  g_C[(size_t)BB * LL * LL];

// ---------------------------------------------------------------------------
__device__ __forceinline__ void mma_f16(float c[4],
                                        uint32_t a0, uint32_t a1, uint32_t a2, uint32_t a3,
                                        uint32_t b0, uint32_t b1)
{
    asm volatile(
        "mma.sync.aligned.m16n8k16.row.col.f32.f16.f16.f32 "
        "{%0,%1,%2,%3}, {%4,%5,%6,%7}, {%8,%9}, {%0,%1,%2,%3};"
        : "+f"(c[0]), "+f"(c[1]), "+f"(c[2]), "+f"(c[3])
        : "r"(a0), "r"(a1), "r"(a2), "r"(a3), "r"(b0), "r"(b1));
}
__device__ __forceinline__ void ldsm4(uint32_t r[4], uint32_t addr)
{
    asm volatile("ldmatrix.sync.aligned.m8n8.x4.shared.b16 {%0,%1,%2,%3}, [%4];"
                 : "=r"(r[0]), "=r"(r[1]), "=r"(r[2]), "=r"(r[3]) : "r"(addr));
}

// Branch-free exact-GELU: erf via Abramowitz-Stegun 7.1.26 (|err| <= 1.5e-7).
__device__ __forceinline__ float fast_gelu(float v)
{
    float z   = v * 0.70710678118654752f;
    float az  = fabsf(z);
    float den = fmaf(0.3275911f, az, 1.0f);
    float t;
    asm("rcp.approx.f32 %0, %1;" : "=f"(t) : "f"(den));
    float e = __expf(-z * z);
    float p = fmaf(1.061405429f, t, -1.453152027f);
    p = fmaf(p, t, 1.421413741f);
    p = fmaf(p, t, -0.284496736f);
    p = fmaf(p, t, 0.254829592f);
    p = p * t;
    float erfa = fmaf(-p, e, 1.0f);        // erf(|z|)
    float erfv = copysignf(erfa, z);
    return 0.5f * v * (1.0f + erfv);
}

// ---------------------------------------------------------------------------
// Kernel 0: one-time transpose W_bil[k][d][e] (fp32) -> g_WbT[k][e][d-pairs] (fp16)
// ---------------------------------------------------------------------------
__global__ __launch_bounds__(256, 2) void k0_transpose(const float* __restrict__ Wb)
{
    __shared__ __half Sg[128 * 130];
    const int k   = blockIdx.x;
    const int tid = threadIdx.x;
    const float* Wk = Wb + (size_t)k * DD * DD;

    #pragma unroll
    for (int s = 0; s < 16; ++s) {
        int v = tid + (s << 8);
        int d = v >> 5, e4 = (v & 31) << 2;
        float4 w = *(const float4*)&Wk[d * DD + e4];
        __half2* dst = (__half2*)&Sg[d * 130 + e4];
        dst[0] = __floats2half2_rn(w.x, w.y);
        dst[1] = __floats2half2_rn(w.z, w.w);
    }
    __syncthreads();

    __half2* out = g_WbT + (size_t)k * (DD * 64);
    #pragma unroll
    for (int s = 0; s < 32; ++s) {
        int v = tid + (s << 8);
        int e = v >> 6, d2 = v & 63;
        __half lo = Sg[(2 * d2) * 130 + e];
        __half hi = Sg[(2 * d2 + 1) * 130 + e];
        out[e * 64 + d2] = __halves2half2(lo, hi);
    }
}

// ---------------------------------------------------------------------------
// Kernel 1 (fp16 mma + ldmatrix): tmp[bi][k][e] = sum_d x[bi][d]*W_bil[k][d][e]
// ---------------------------------------------------------------------------
#define K1_XS 0u
#define K1_WT 34816u
#define K1_SMEM 69632u

__global__ __launch_bounds__(256, 2) void k1_tmp(const float* __restrict__ x)
{
    extern __shared__ char smc[];
    __half2* Xs = (__half2*)(smc + K1_XS);
    __half2* Wt = (__half2*)(smc + K1_WT);

    const int k   = blockIdx.x;
    const int bi0 = blockIdx.y * 128;
    const int tid = threadIdx.x, tx = tid & 31, wid = tid >> 5;
    const int wj  = wid & 3, wk = wid >> 2;
    const int g   = tx >> 2, c = tx & 3;
    const int arow = wj * 32, bcol = wk * 64;

    const __half2* Wsrc = g_WbT + (size_t)k * (DD * 64);
    #pragma unroll
    for (int s = 0; s < 8; ++s) {
        int v = tid + (s << 8);
        int row = v >> 4, u = (v & 15) << 2;
        uint4 t = *(const uint4*)&Wsrc[row * 64 + u];
        *(uint4*)&Wt[row * HP + u] = t;
    }
    #pragma unroll
    for (int s = 0; s < 16; ++s) {
        int v = tid + (s << 8);
        int row = v >> 5, d4 = (v & 31) << 2;
        int bi = bi0 + row;
        __half2 h0, h1;
        if (bi < NBI) {
            float4 t = *(const float4*)&x[(size_t)bi * DD + d4];
            h0 = __floats2half2_rn(t.x, t.y);
            h1 = __floats2half2_rn(t.z, t.w);
        } else {
            h0 = __floats2half2_rn(0.f, 0.f); h1 = h0;
        }
        Xs[row * HP + (d4 >> 1)]     = h0;
        Xs[row * HP + (d4 >> 1) + 1] = h1;
    }
    __syncthreads();

    const uint32_t sb  = (uint32_t)__cvta_generic_to_shared(smc);
    const uint32_t sbX = sb + K1_XS, sbW = sb + K1_WT;

    uint32_t aAddr[2], bOff[4];
    #pragma unroll
    for (int mf = 0; mf < 2; ++mf) {
        int row = arow + mf * 16 + (tx & 7) + ((tx & 8) ? 8 : 0);
        aAddr[mf] = sbX + row * 272 + ((tx & 16) ? 16 : 0);
    }
    #pragma unroll
    for (int p = 0; p < 4; ++p) {
        int row = bcol + p * 16 + (tx & 7) + ((tx & 16) ? 8 : 0);
        bOff[p] = row * 272 + ((tx & 8) ? 16 : 0);
    }

    float acc[2][8][4];
    #pragma unroll
    for (int mf = 0; mf < 2; ++mf)
        #pragma unroll
        for (int nt = 0; nt < 8; ++nt)
            #pragma unroll
            for (int u = 0; u < 4; ++u) acc[mf][nt][u] = 0.0f;

    #pragma unroll
    for (int kc = 0; kc < 8; ++kc) {
        int ko = kc * 32;
        uint32_t a0[4], a1[4];
        ldsm4(a0, aAddr[0] + ko);
        ldsm4(a1, aAddr[1] + ko);
        #pragma unroll
        for (int p = 0; p < 4; ++p) {
            uint32_t bb[4];
            ldsm4(bb, sbW + bOff[p] + ko);
            mma_f16(acc[0][2 * p],     a0[0], a0[1], a0[2], a0[3], bb[0], bb[1]);
            mma_f16(acc[1][2 * p],     a1[0], a1[1], a1[2], a1[3], bb[0], bb[1]);
            mma_f16(acc[0][2 * p + 1], a0[0], a0[1], a0[2], a0[3], bb[2], bb[3]);
            mma_f16(acc[1][2 * p + 1], a1[0], a1[1], a1[2], a1[3], bb[2], bb[3]);
        }
    }

    #pragma unroll
    for (int mf = 0; mf < 2; ++mf)
        #pragma unroll
        for (int nt = 0; nt < 8; ++nt) {
            int r0  = bi0 + arow + mf * 16 + g;
            int col = bcol + nt * 8 + 2 * c;
            if (r0 < NBI)
                *(__half2*)&g_tmp_h[(size_t)r0 * (DD * DD) + k * DD + col] =
                    __floats2half2_rn(acc[mf][nt][0], acc[mf][nt][1]);
            int r1 = r0 + 8;
            if (r1 < NBI)
                *(__half2*)&g_tmp_h[(size_t)r1 * (DD * DD) + k * DD + col] =
                    __floats2half2_rn(acc[mf][nt][2], acc[mf][nt][3]);
        }
}

// ---------------------------------------------------------------------------
// Kernel 2 (fp16 mma + ldmatrix): per (b,i) CTA, fused, tiles {128,128,128,32}.
// ---------------------------------------------------------------------------
#define K2_TS 0u
#define K2_WS 34816u
#define K2_XS 69632u
#define K2_CV 104448u
#define K2_RA 107008u
#define K2_RB 109056u
#define K2_SMEM 110080u

__global__ __launch_bounds__(256, 2) void k2_fused(
    const float* __restrict__ x,    const float* __restrict__ b_bil,
    const float* __restrict__ ln_g, const float* __restrict__ ln_b,
    const float* __restrict__ W1,   const float* __restrict__ b1,
    const float* __restrict__ w2,   const float* __restrict__ b2)
{
    extern __shared__ char smc[];
    __half2* Ts  = (__half2*)(smc + K2_TS);
    __half2* W1s = (__half2*)(smc + K2_WS);
    __half2* Xs  = (__half2*)(smc + K2_XS);
    float* cv  = (float*)(smc + K2_CV);
    float* bbs = cv;        float* lgs = cv + 128; float* lbs = cv + 256;
    float* b1s = cv + 384;  float* w2s = cv + 512;
    float2* redA = (float2*)(smc + K2_RA);
    float*  redB = (float*) (smc + K2_RB);

    const int bi  = blockIdx.x;
    const int b   = bi / LL;
    const int tid = threadIdx.x, tx = tid & 31, wid = tid >> 5;
    const int wj  = wid & 3, wk = wid >> 2;
    const int g   = tx >> 2, c = tx & 3;
    const int arow = wj * 32, bcol = wk * 64;

    const __half* tp = g_tmp_h + (size_t)bi * DD * DD;
    #pragma unroll
    for (int s = 0; s < 8; ++s) {
        int v = tid + (s << 8);
        int row = v >> 4, seg = (v & 15) << 3;
        uint4 tv = *(const uint4*)&tp[row * DD + seg];
        *(uint4*)((char*)Ts + row * 272 + seg * 2) = tv;
        const float* wp = &W1[row * DD + seg];
        float4 u0 = *(const float4*)wp;
        float4 u1 = *(const float4*)(wp + 4);
        __half2* d = (__half2*)((char*)W1s + row * 272 + seg * 2);
        d[0] = __floats2half2_rn(u0.x, u0.y);
        d[1] = __floats2half2_rn(u0.z, u0.w);
        d[2] = __floats2half2_rn(u1.x, u1.y);
        d[3] = __floats2half2_rn(u1.z, u1.w);
    }
    if (tid < 128) {
        bbs[tid] = b_bil[tid]; lgs[tid] = ln_g[tid]; lbs[tid] = ln_b[tid];
        b1s[tid] = b1[tid];    w2s[tid] = w2[tid];
    }
    const float b2v = b2[0];
    const float* xb = x + (size_t)b * LL * DD;
    float* Crow = g_C + (size_t)bi * LL;

    const uint32_t sb  = (uint32_t)__cvta_generic_to_shared(smc);
    const uint32_t sbX = sb + K2_XS, sbT = sb + K2_TS, sbW = sb + K2_WS;

    uint32_t aAddr[2], bOff[4];
    #pragma unroll
    for (int mf = 0; mf < 2; ++mf) {
        int row = arow + mf * 16 + (tx & 7) + ((tx & 8) ? 8 : 0);
        aAddr[mf] = sbX + row * 272 + ((tx & 16) ? 16 : 0);
    }
    #pragma unroll
    for (int p = 0; p < 4; ++p) {
        int row = bcol + p * 16 + (tx & 7) + ((tx & 16) ? 8 : 0);
        bOff[p] = row * 272 + ((tx & 8) ? 16 : 0);
    }
    __syncthreads();

    #pragma unroll 1
    for (int t = 0; t < 4; ++t) {
        const int j0 = t * 128;
        const int mrows = (t == 3) ? 32 : 128;
        const bool active = (arow < mrows);

        // ---- Load x_j tile (fp16, zero-pad) ----
        #pragma unroll
        for (int s = 0; s < 8; ++s) {
            int v = tid + (s << 8);
            int row = v >> 4, seg = (v & 15) << 3;
            int j = j0 + row;
            __half2* d = (__half2*)((char*)Xs + row * 272 + seg * 2);
            if (j < LL) {
                const float* sp = &xb[(size_t)j * DD + seg];
                float4 u0 = *(const float4*)sp;
                float4 u1 = *(const float4*)(sp + 4);
                d[0] = __floats2half2_rn(u0.x, u0.y);
                d[1] = __floats2half2_rn(u0.z, u0.w);
                d[2] = __floats2half2_rn(u1.x, u1.y);
                d[3] = __floats2half2_rn(u1.z, u1.w);
            } else {
                __half2 z = __floats2half2_rn(0.f, 0.f);
                d[0] = z; d[1] = z; d[2] = z; d[3] = z;
            }
        }
        __syncthreads();

        float acc[2][8][4];
        float s1[4], s2[4];
        if (active) {
            // ---- Phase A: pair = X @ Ts^T ----
            #pragma unroll
            for (int mf = 0; mf < 2; ++mf)
                #pragma unroll
                for (int nt = 0; nt < 8; ++nt)
                    #pragma unroll
                    for (int u = 0; u < 4; ++u) acc[mf][nt][u] = 0.0f;

            #pragma unroll
            for (int kc = 0; kc < 8; ++kc) {
                int ko = kc * 32;
                uint32_t a0[4], a1[4];
                ldsm4(a0, aAddr[0] + ko);
                ldsm4(a1, aAddr[1] + ko);
                #pragma unroll
                for (int p = 0; p < 4; ++p) {
                    uint32_t bb[4];
                    ldsm4(bb, sbT + bOff[p] + ko);
                    mma_f16(acc[0][2 * p],     a0[0], a0[1], a0[2], a0[3], bb[0], bb[1]);
                    mma_f16(acc[1][2 * p],     a1[0], a1[1], a1[2], a1[3], bb[0], bb[1]);
                    mma_f16(acc[0][2 * p + 1], a0[0], a0[1], a0[2], a0[3], bb[2], bb[3]);
                    mma_f16(acc[1][2 * p + 1], a1[0], a1[1], a1[2], a1[3], bb[2], bb[3]);
                }
            }

            // ---- LN stats ----
            #pragma unroll
            for (int lr = 0; lr < 4; ++lr) { s1[lr] = 0.f; s2[lr] = 0.f; }
            #pragma unroll
            for (int mf = 0; mf < 2; ++mf)
                #pragma unroll
                for (int nt = 0; nt < 8; ++nt) {
                    int col = bcol + nt * 8 + 2 * c;
                    float bb0 = bbs[col], bb1 = bbs[col + 1];
                    acc[mf][nt][0] += bb0; acc[mf][nt][1] += bb1;
                    acc[mf][nt][2] += bb0; acc[mf][nt][3] += bb1;
                    s1[mf * 2]     += acc[mf][nt][0] + acc[mf][nt][1];
                    s2[mf * 2]     += acc[mf][nt][0] * acc[mf][nt][0] + acc[mf][nt][1] * acc[mf][nt][1];
                    s1[mf * 2 + 1] += acc[mf][nt][2] + acc[mf][nt][3];
                    s2[mf * 2 + 1] += acc[mf][nt][2] * acc[mf][nt][2] + acc[mf][nt][3] * acc[mf][nt][3];
                }
            #pragma unroll
            for (int off = 1; off <= 2; off <<= 1)
                #pragma unroll
                for (int lr = 0; lr < 4; ++lr) {
                    s1[lr] += __shfl_xor_sync(0xffffffffu, s1[lr], off);
                    s2[lr] += __shfl_xor_sync(0xffffffffu, s2[lr], off);
                }
            if (c == 0) {
                #pragma unroll
                for (int lr = 0; lr < 4; ++lr) {
                    int row = arow + (lr >> 1) * 16 + (lr & 1) * 8 + g;
                    redA[row * 2 + wk] = make_float2(s1[lr], s2[lr]);
                }
            }
        }
        __syncthreads();

        if (active) {
            float mu[4], rs[4];
            #pragma unroll
            for (int lr = 0; lr < 4; ++lr) {
                int row = arow + (lr >> 1) * 16 + (lr & 1) * 8 + g;
                float2 rA = redA[row * 2 + 0], rB = redA[row * 2 + 1];
                float S1 = rA.x + rB.x, S2 = rA.y + rB.y;
                mu[lr] = S1 * (1.0f / 128.0f);
                rs[lr] = rsqrtf(S2 * (1.0f / 128.0f) - mu[lr] * mu[lr] + 1e-5f);
            }
            // ---- Write H (fp16) into Xs ----
            #pragma unroll
            for (int mf = 0; mf < 2; ++mf)
                #pragma unroll
                for (int nt = 0; nt < 8; ++nt) {
                    int col = bcol + nt * 8 + 2 * c;
                    int h2i = (col >> 1);
                    float lg0 = lgs[col], lg1 = lgs[col + 1];
                    float lb0 = lbs[col], lb1 = lbs[col + 1];
                    int lr0 = mf * 2, lr1 = mf * 2 + 1;
                    int r0 = arow + mf * 16 + g;
                    Xs[r0 * HP + h2i] = __floats2half2_rn(
                        (acc[mf][nt][0] - mu[lr0]) * rs[lr0] * lg0 + lb0,
                        (acc[mf][nt][1] - mu[lr0]) * rs[lr0] * lg1 + lb1);
                    Xs[(r0 + 8) * HP + h2i] = __floats2half2_rn(
                        (acc[mf][nt][2] - mu[lr1]) * rs[lr1] * lg0 + lb0,
                        (acc[mf][nt][3] - mu[lr1]) * rs[lr1] * lg1 + lb1);
                }
        }
        __syncthreads();

        if (active) {
            // ---- Phase B: o = H @ W1^T ----
            #pragma unroll
            for (int mf = 0; mf < 2; ++mf)
                #pragma unroll
                for (int nt = 0; nt < 8; ++nt)
                    #pragma unroll
                    for (int u = 0; u < 4; ++u) acc[mf][nt][u] = 0.0f;

            #pragma unroll
            for (int kc = 0; kc < 8; ++kc) {
                int ko = kc * 32;
                uint32_t a0[4], a1[4];
                ldsm4(a0, aAddr[0] + ko);
                ldsm4(a1, aAddr[1] + ko);
                #pragma unroll
                for (int p = 0; p < 4; ++p) {
                    uint32_t bb[4];
                    ldsm4(bb, sbW + bOff[p] + ko);
                    mma_f16(acc[0][2 * p],     a0[0], a0[1], a0[2], a0[3], bb[0], bb[1]);
                    mma_f16(acc[1][2 * p],     a1[0], a1[1], a1[2], a1[3], bb[0], bb[1]);
                    mma_f16(acc[0][2 * p + 1], a0[0], a0[1], a0[2], a0[3], bb[2], bb[3]);
                    mma_f16(acc[1][2 * p + 1], a1[0], a1[1], a1[2], a1[3], bb[2], bb[3]);
                }
            }

            // ---- Epilogue: bias, branch-free GELU, dot w2 ----
            float tsum[4] = {0.f, 0.f, 0.f, 0.f};
            #pragma unroll
            for (int mf = 0; mf < 2; ++mf)
                #pragma unroll
                for (int nt = 0; nt < 8; ++nt) {
                    int col = bcol + nt * 8 + 2 * c;
                    float c0 = b1s[col], c1 = b1s[col + 1];
                    float w0 = w2s[col], w1 = w2s[col + 1];
                    tsum[mf * 2]     += fast_gelu(acc[mf][nt][0] + c0) * w0
                                      + fast_gelu(acc[mf][nt][1] + c1) * w1;
                    tsum[mf * 2 + 1] += fast_gelu(acc[mf][nt][2] + c0) * w0
                                      + fast_gelu(acc[mf][nt][3] + c1) * w1;
                }
            #pragma unroll
            for (int off = 1; off <= 2; off <<= 1)
                #pragma unroll
                for (int lr = 0; lr < 4; ++lr)
                    tsum[lr] += __shfl_xor_sync(0xffffffffu, tsum[lr], off);
            if (c == 0) {
                #pragma unroll
                for (int lr = 0; lr < 4; ++lr) {
                    int row = arow + (lr >> 1) * 16 + (lr & 1) * 8 + g;
                    redB[row * 2 + wk] = tsum[lr];
                }
            }
        }
        __syncthreads();

        if (tid < mrows) {
            int j = j0 + tid;
            if (j < LL) Crow[j] = redB[tid * 2] + redB[tid * 2 + 1] + b2v;
        }
        // no trailing sync: C-write reads redB only; next tile writes Xs (disjoint)
    }
}

// ---------------------------------------------------------------------------
// Kernel 3: out[b,i,j] = 0.5*(C[b,i,j] + C[b,j,i]) with smem tile transpose.
// ---------------------------------------------------------------------------
__global__ __launch_bounds__(256) void k3_sym(float* __restrict__ out)
{
    __shared__ float tA[32][33];
    __shared__ float tB[32][33];
    const int b  = blockIdx.z;
    const int i0 = blockIdx.y * 32, j0 = blockIdx.x * 32;
    const int tx = threadIdx.x & 31, ty = threadIdx.x >> 5;
    const float* Cb = g_C + (size_t)b * LL * LL;

    #pragma unroll
    for (int r = 0; r < 4; ++r) {
        int row = ty + r * 8;
        int gi = i0 + row, gj = j0 + tx;
        tA[row][tx] = (gi < LL && gj < LL) ? Cb[gi * LL + gj] : 0.f;
        int hi = j0 + row, hj = i0 + tx;
        tB[row][tx] = (hi < LL && hj < LL) ? Cb[hi * LL + hj] : 0.f;
    }
    __syncthreads();

    float* Ob = out + (size_t)b * LL * LL;
    #pragma unroll
    for (int r = 0; r < 4; ++r) {
        int row = ty + r * 8;
        int gi = i0 + row, gj = j0 + tx;
        if (gi < LL && gj < LL)
            Ob[gi * LL + gj] = 0.5f * (tA[row][tx] + tB[tx][row]);
    }
}

// ---------------------------------------------------------------------------
extern "C" void kernel_launch(void* const* d_in, const int* in_sizes, int n_in,
                              void* d_out, int out_size)
{
    (void)in_sizes; (void)n_in; (void)out_size;
    const float* x     = (const float*)d_in[0];
    const float* W_bil = (const float*)d_in[1];
    const float* b_bil = (const float*)d_in[2];
    const float* ln_g  = (const float*)d_in[3];
    const float* ln_b  = (const float*)d_in[4];
    const float* W1    = (const float*)d_in[5];
    const float* b1    = (const float*)d_in[6];
    const float* w2    = (const float*)d_in[7];
    const float* b2    = (const float*)d_in[8];
    float* out = (float*)d_out;

    cudaFuncSetAttribute(k1_tmp,   cudaFuncAttributeMaxDynamicSharedMemorySize, K1_SMEM);
    cudaFuncSetAttribute(k2_fused, cudaFuncAttributeMaxDynamicSharedMemorySize, K2_SMEM);

    k0_transpose<<<128, 256>>>(W_bil);
    dim3 g1(128, (NBI + 127) / 128);   // 128 x 7
    k1_tmp<<<g1, 256, K1_SMEM>>>(x);
    k2_fused<<<NBI, 256, K2_SMEM>>>(x, b_bil, ln_g, ln_b, W1, b1, w2, b2);

    dim3 g3((LL + 31) / 32, (LL + 31) / 32, BB);   // 13 x 13 x 2
    k3_sym<<<g3, 256>>>(out);
}

// round 10
// speedup vs baseline: 2.3126x; 1.1681x over previous
#include <cuda_runtime.h>
#include <cuda_fp16.h>
#include <math.h>
#include <stdint.h>

#define BB 2
#define LL 401
#define DD 128
#define NBI (BB*LL)   // 802
#define HP 68         // smem row pitch in half2 (136 halfs, 272 B)

__device__ __half g_tmp_h[(size_t)NBI * DD * DD];             // 26.3 MB tmp[b,i,k,e] fp16
__device__ __align__(16) __half2 g_WbT[(size_t)DD * DD * 64]; // 4 MB: [k][e][d-pairs]
__device__ __align__(16) __half  g_x_h[(size_t)BB * 512 * DD];// padded fp16 x: [b][512][128]
__device__ float  g_C[(size_t)BB * LL * LL];

// ---------------------------------------------------------------------------
__device__ __forceinline__ void mma_f16(float c[4],
                                        uint32_t a0, uint32_t a1, uint32_t a2, uint32_t a3,
                                        uint32_t b0, uint32_t b1)
{
    asm volatile(
        "mma.sync.aligned.m16n8k16.row.col.f32.f16.f16.f32 "
        "{%0,%1,%2,%3}, {%4,%5,%6,%7}, {%8,%9}, {%0,%1,%2,%3};"
        : "+f"(c[0]), "+f"(c[1]), "+f"(c[2]), "+f"(c[3])
        : "r"(a0), "r"(a1), "r"(a2), "r"(a3), "r"(b0), "r"(b1));
}
__device__ __forceinline__ void ldsm4(uint32_t r[4], uint32_t addr)
{
    asm volatile("ldmatrix.sync.aligned.m8n8.x4.shared.b16 {%0,%1,%2,%3}, [%4];"
                 : "=r"(r[0]), "=r"(r[1]), "=r"(r[2]), "=r"(r[3]) : "r"(addr));
}
__device__ __forceinline__ void barp(int id)
{
    asm volatile("bar.sync %0, 64;" :: "r"(id) : "memory");
}

// Branch-free GELU WITHOUT the 0.5 (folded into w2): v*(1+erf(v/sqrt2))
__device__ __forceinline__ float gelu2x(float v)
{
    float z   = v * 0.70710678118654752f;
    float az  = fabsf(z);
    float den = fmaf(0.3275911f, az, 1.0f);
    float t;
    asm("rcp.approx.f32 %0, %1;" : "=f"(t) : "f"(den));
    float e = __expf(-z * z);
    float p = fmaf(1.061405429f, t, -1.453152027f);
    p = fmaf(p, t, 1.421413741f);
    p = fmaf(p, t, -0.284496736f);
    p = fmaf(p, t, 0.254829592f);
    p = p * t;
    float erfa = fmaf(-p, e, 1.0f);
    float erfv = copysignf(erfa, z);
    return v * (1.0f + erfv);
}

// ---------------------------------------------------------------------------
// Kernel 0: one-time transpose W_bil[k][d][e] (fp32) -> g_WbT[k][e][d-pairs] (fp16)
// ---------------------------------------------------------------------------
__global__ __launch_bounds__(256, 2) void k0_transpose(const float* __restrict__ Wb)
{
    __shared__ __half Sg[128 * 130];
    const int k   = blockIdx.x;
    const int tid = threadIdx.x;
    const float* Wk = Wb + (size_t)k * DD * DD;

    #pragma unroll
    for (int s = 0; s < 16; ++s) {
        int v = tid + (s << 8);
        int d = v >> 5, e4 = (v & 31) << 2;
        float4 w = *(const float4*)&Wk[d * DD + e4];
        __half2* dst = (__half2*)&Sg[d * 130 + e4];
        dst[0] = __floats2half2_rn(w.x, w.y);
        dst[1] = __floats2half2_rn(w.z, w.w);
    }
    __syncthreads();

    __half2* out = g_WbT + (size_t)k * (DD * 64);
    #pragma unroll
    for (int s = 0; s < 32; ++s) {
        int v = tid + (s << 8);
        int e = v >> 6, d2 = v & 63;
        __half lo = Sg[(2 * d2) * 130 + e];
        __half hi = Sg[(2 * d2 + 1) * 130 + e];
        out[e * 64 + d2] = __halves2half2(lo, hi);
    }
}

// ---------------------------------------------------------------------------
// Kernel 0x: convert x (fp32) -> g_x_h fp16, padded to 512 rows per b.
// ---------------------------------------------------------------------------
__global__ __launch_bounds__(256) void k0x_convert(const float* __restrict__ x)
{
    int idx = blockIdx.x * 256 + threadIdx.x;   // one half2 each; 2*512*64 total
    if (idx >= BB * 512 * 64) return;
    int b   = idx >> 15;            // 512*64 per b
    int rem = idx & 32767;
    int r   = rem >> 6, c2 = rem & 63;
    __half2 h;
    if (r < LL) {
        const float* sp = &x[((size_t)(b * LL + r)) * DD + c2 * 2];
        h = __floats2half2_rn(sp[0], sp[1]);
    } else {
        h = __floats2half2_rn(0.f, 0.f);
    }
    *(__half2*)&g_x_h[((size_t)(b * 512 + r)) * DD + c2 * 2] = h;
}

// ---------------------------------------------------------------------------
// Kernel 1 (fp16 mma + ldmatrix): tmp[bi][k][e] = sum_d x[bi][d]*W_bil[k][d][e]
// ---------------------------------------------------------------------------
#define K1_XS 0u
#define K1_WT 34816u
#define K1_SMEM 69632u

__global__ __launch_bounds__(256, 2) void k1_tmp()
{
    extern __shared__ char smc[];
    __half2* Xs = (__half2*)(smc + K1_XS);
    __half2* Wt = (__half2*)(smc + K1_WT);

    const int k   = blockIdx.x;
    const int bi0 = blockIdx.y * 128;
    const int tid = threadIdx.x, tx = tid & 31, wid = tid >> 5;
    const int wj  = wid & 3, wk = wid >> 2;
    const int g   = tx >> 2, c = tx & 3;
    const int arow = wj * 32, bcol = wk * 64;

    const __half2* Wsrc = g_WbT + (size_t)k * (DD * 64);
    #pragma unroll
    for (int s = 0; s < 8; ++s) {
        int v = tid + (s << 8);
        int row = v >> 4, u = (v & 15) << 2;
        uint4 t = *(const uint4*)&Wsrc[row * 64 + u];
        *(uint4*)&Wt[row * HP + u] = t;
    }
    // x rows: raw fp16 copy from padded g_x_h
    #pragma unroll
    for (int s = 0; s < 8; ++s) {
        int v = tid + (s << 8);          // uint4 units, 2048 total
        int row = v >> 4, seg = v & 15;
        int bi = bi0 + row;
        int bb_ = (bi >= LL) ? 1 : 0;
        int r = bi - bb_ * LL;           // bi<896 -> r<512 (padded zeros)
        uint4 t = *(const uint4*)&g_x_h[((size_t)(bb_ * 512 + r)) * DD + seg * 8];
        *(uint4*)((char*)Xs + row * 272 + seg * 16) = t;
    }
    __syncthreads();

    const uint32_t sb  = (uint32_t)__cvta_generic_to_shared(smc);
    const uint32_t sbX = sb + K1_XS, sbW = sb + K1_WT;

    uint32_t aAddr[2], bOff[4];
    #pragma unroll
    for (int mf = 0; mf < 2; ++mf) {
        int row = arow + mf * 16 + (tx & 7) + ((tx & 8) ? 8 : 0);
        aAddr[mf] = sbX + row * 272 + ((tx & 16) ? 16 : 0);
    }
    #pragma unroll
    for (int p = 0; p < 4; ++p) {
        int row = bcol + p * 16 + (tx & 7) + ((tx & 16) ? 8 : 0);
        bOff[p] = row * 272 + ((tx & 8) ? 16 : 0);
    }

    float acc[2][8][4];
    #pragma unroll
    for (int mf = 0; mf < 2; ++mf)
        #pragma unroll
        for (int nt = 0; nt < 8; ++nt)
            #pragma unroll
            for (int u = 0; u < 4; ++u) acc[mf][nt][u] = 0.0f;

    #pragma unroll
    for (int kc = 0; kc < 8; ++kc) {
        int ko = kc * 32;
        uint32_t a0[4], a1[4];
        ldsm4(a0, aAddr[0] + ko);
        ldsm4(a1, aAddr[1] + ko);
        #pragma unroll
        for (int p = 0; p < 4; ++p) {
            uint32_t bb[4];
            ldsm4(bb, sbW + bOff[p] + ko);
            mma_f16(acc[0][2 * p],     a0[0], a0[1], a0[2], a0[3], bb[0], bb[1]);
            mma_f16(acc[1][2 * p],     a1[0], a1[1], a1[2], a1[3], bb[0], bb[1]);
            mma_f16(acc[0][2 * p + 1], a0[0], a0[1], a0[2], a0[3], bb[2], bb[3]);
            mma_f16(acc[1][2 * p + 1], a1[0], a1[1], a1[2], a1[3], bb[2], bb[3]);
        }
    }

    #pragma unroll
    for (int mf = 0; mf < 2; ++mf)
        #pragma unroll
        for (int nt = 0; nt < 8; ++nt) {
            int r0  = bi0 + arow + mf * 16 + g;
            int col = bcol + nt * 8 + 2 * c;
            if (r0 < NBI)
                *(__half2*)&g_tmp_h[(size_t)r0 * (DD * DD) + k * DD + col] =
                    __floats2half2_rn(acc[mf][nt][0], acc[mf][nt][1]);
            int r1 = r0 + 8;
            if (r1 < NBI)
                *(__half2*)&g_tmp_h[(size_t)r1 * (DD * DD) + k * DD + col] =
                    __floats2half2_rn(acc[mf][nt][2], acc[mf][nt][3]);
        }
}

// ---------------------------------------------------------------------------
// Kernel 2: per (b,i) CTA, fused. WARP-PAIR independent: pair (wj, wj+4) owns
// j-rows [arow, arow+32) end-to-end; all intra-tile syncs are bar.sync(wj+1,64).
// ---------------------------------------------------------------------------
#define K2_TS 0u
#define K2_WS 34816u
#define K2_XS 69632u
#define K2_CV 104448u
#define K2_RA 107008u
#define K2_RB 109056u
#define K2_SMEM 110080u

__global__ __launch_bounds__(256, 2) void k2_fused(
    const float* __restrict__ b_bil,
    const float* __restrict__ ln_g, const float* __restrict__ ln_b,
    const float* __restrict__ W1,   const float* __restrict__ b1,
    const float* __restrict__ w2,   const float* __restrict__ b2)
{
    extern __shared__ char smc[];
    __half2* Ts  = (__half2*)(smc + K2_TS);
    __half2* W1s = (__half2*)(smc + K2_WS);
    __half2* Xs  = (__half2*)(smc + K2_XS);
    float* cv  = (float*)(smc + K2_CV);
    float* bbs = cv;        float* lgs = cv + 128; float* lbs = cv + 256;
    float* b1s = cv + 384;  float* w2s = cv + 512;
    float2* redA = (float2*)(smc + K2_RA);
    float*  redB = (float*) (smc + K2_RB);

    const int bi  = blockIdx.x;
    const int b   = bi / LL;
    const int tid = threadIdx.x, tx = tid & 31, wid = tid >> 5;
    const int wj  = wid & 3, wk = wid >> 2;
    const int g   = tx >> 2, c = tx & 3;
    const int arow = wj * 32, bcol = wk * 64;
    const int pt  = wk * 32 + tx;          // thread index within pair [0,64)
    const int pb  = wj + 1;                // named barrier id

    const __half* tp = g_tmp_h + (size_t)bi * DD * DD;
    #pragma unroll
    for (int s = 0; s < 8; ++s) {
        int v = tid + (s << 8);
        int row = v >> 4, seg = (v & 15) << 3;
        uint4 tv = *(const uint4*)&tp[row * DD + seg];
        *(uint4*)((char*)Ts + row * 272 + seg * 2) = tv;
        const float* wp = &W1[row * DD + seg];
        float4 u0 = *(const float4*)wp;
        float4 u1 = *(const float4*)(wp + 4);
        __half2* d = (__half2*)((char*)W1s + row * 272 + seg * 2);
        d[0] = __floats2half2_rn(u0.x, u0.y);
        d[1] = __floats2half2_rn(u0.z, u0.w);
        d[2] = __floats2half2_rn(u1.x, u1.y);
        d[3] = __floats2half2_rn(u1.z, u1.w);
    }
    if (tid < 128) {
        bbs[tid] = b_bil[tid]; lgs[tid] = ln_g[tid]; lbs[tid] = ln_b[tid];
        b1s[tid] = b1[tid];    w2s[tid] = 0.5f * w2[tid];   // GELU 0.5 folded
    }
    const float b2v = b2[0];
    const __half* xh = g_x_h + (size_t)b * 512 * DD;
    float* Crow = g_C + (size_t)bi * LL;

    const uint32_t sb  = (uint32_t)__cvta_generic_to_shared(smc);
    const uint32_t sbX = sb + K2_XS, sbT = sb + K2_TS, sbW = sb + K2_WS;

    uint32_t aAddr[2], bOff[4];
    #pragma unroll
    for (int mf = 0; mf < 2; ++mf) {
        int row = arow + mf * 16 + (tx & 7) + ((tx & 8) ? 8 : 0);
        aAddr[mf] = sbX + row * 272 + ((tx & 16) ? 16 : 0);
    }
    #pragma unroll
    for (int p = 0; p < 4; ++p) {
        int row = bcol + p * 16 + (tx & 7) + ((tx & 16) ? 8 : 0);
        bOff[p] = row * 272 + ((tx & 8) ? 16 : 0);
    }
    __syncthreads();   // Ts/W1s/constants visible to all; last CTA-wide sync

    #pragma unroll 1
    for (int t = 0; t < 4; ++t) {
        const int j0 = t * 128;
        const int mrows = (t == 3) ? 32 : 128;
        if (arow >= mrows) continue;   // whole pair skips tail together

        // ---- Pair loads its own 32 X rows (raw fp16 copy) ----
        #pragma unroll
        for (int s = 0; s < 8; ++s) {
            int u = pt + (s << 6);          // uint4 units, 512 per pair
            int row = arow + (u >> 4), seg = u & 15;
            uint4 tv = *(const uint4*)&xh[((size_t)(j0 + row)) * DD + seg * 8];
            *(uint4*)((char*)Xs + row * 272 + seg * 16) = tv;
        }
        barp(pb);

        // ---- Phase A: pair = X @ Ts^T ----
        float acc[2][8][4];
        #pragma unroll
        for (int mf = 0; mf < 2; ++mf)
            #pragma unroll
            for (int nt = 0; nt < 8; ++nt)
                #pragma unroll
                for (int u = 0; u < 4; ++u) acc[mf][nt][u] = 0.0f;

        #pragma unroll
        for (int kc = 0; kc < 8; ++kc) {
            int ko = kc * 32;
            uint32_t a0[4], a1[4];
            ldsm4(a0, aAddr[0] + ko);
            ldsm4(a1, aAddr[1] + ko);
            #pragma unroll
            for (int p = 0; p < 4; ++p) {
                uint32_t bb[4];
                ldsm4(bb, sbT + bOff[p] + ko);
                mma_f16(acc[0][2 * p],     a0[0], a0[1], a0[2], a0[3], bb[0], bb[1]);
                mma_f16(acc[1][2 * p],     a1[0], a1[1], a1[2], a1[3], bb[0], bb[1]);
                mma_f16(acc[0][2 * p + 1], a0[0], a0[1], a0[2], a0[3], bb[2], bb[3]);
                mma_f16(acc[1][2 * p + 1], a1[0], a1[1], a1[2], a1[3], bb[2], bb[3]);
            }
        }

        // ---- LN stats ----
        float s1[4] = {0.f, 0.f, 0.f, 0.f}, s2[4] = {0.f, 0.f, 0.f, 0.f};
        #pragma unroll
        for (int mf = 0; mf < 2; ++mf)
            #pragma unroll
            for (int nt = 0; nt < 8; ++nt) {
                int col = bcol + nt * 8 + 2 * c;
                float bb0 = bbs[col], bb1 = bbs[col + 1];
                acc[mf][nt][0] += bb0; acc[mf][nt][1] += bb1;
                acc[mf][nt][2] += bb0; acc[mf][nt][3] += bb1;
                s1[mf * 2]     += acc[mf][nt][0] + acc[mf][nt][1];
                s2[mf * 2]     += acc[mf][nt][0] * acc[mf][nt][0] + acc[mf][nt][1] * acc[mf][nt][1];
                s1[mf * 2 + 1] += acc[mf][nt][2] + acc[mf][nt][3];
                s2[mf * 2 + 1] += acc[mf][nt][2] * acc[mf][nt][2] + acc[mf][nt][3] * acc[mf][nt][3];
            }
        #pragma unroll
        for (int off = 1; off <= 2; off <<= 1)
            #pragma unroll
            for (int lr = 0; lr < 4; ++lr) {
                s1[lr] += __shfl_xor_sync(0xffffffffu, s1[lr], off);
                s2[lr] += __shfl_xor_sync(0xffffffffu, s2[lr], off);
            }
        if (c == 0) {
            #pragma unroll
            for (int lr = 0; lr < 4; ++lr) {
                int row = arow + (lr >> 1) * 16 + (lr & 1) * 8 + g;
                redA[row * 2 + wk] = make_float2(s1[lr], s2[lr]);
            }
        }
        barp(pb);

        float mu[4], rs[4];
        #pragma unroll
        for (int lr = 0; lr < 4; ++lr) {
            int row = arow + (lr >> 1) * 16 + (lr & 1) * 8 + g;
            float2 rA = redA[row * 2 + 0], rB = redA[row * 2 + 1];
            float S1 = rA.x + rB.x, S2 = rA.y + rB.y;
            mu[lr] = S1 * (1.0f / 128.0f);
            rs[lr] = rsqrtf(S2 * (1.0f / 128.0f) - mu[lr] * mu[lr] + 1e-5f);
        }
        // ---- Write H (fp16) into Xs (own rows) ----
        #pragma unroll
        for (int mf = 0; mf < 2; ++mf)
            #pragma unroll
            for (int nt = 0; nt < 8; ++nt) {
                int col = bcol + nt * 8 + 2 * c;
                int h2i = (col >> 1);
                float lg0 = lgs[col], lg1 = lgs[col + 1];
                float lb0 = lbs[col], lb1 = lbs[col + 1];
                int lr0 = mf * 2, lr1 = mf * 2 + 1;
                int r0 = arow + mf * 16 + g;
                Xs[r0 * HP + h2i] = __floats2half2_rn(
                    (acc[mf][nt][0] - mu[lr0]) * rs[lr0] * lg0 + lb0,
                    (acc[mf][nt][1] - mu[lr0]) * rs[lr0] * lg1 + lb1);
                Xs[(r0 + 8) * HP + h2i] = __floats2half2_rn(
                    (acc[mf][nt][2] - mu[lr1]) * rs[lr1] * lg0 + lb0,
                    (acc[mf][nt][3] - mu[lr1]) * rs[lr1] * lg1 + lb1);
            }
        barp(pb);

        // ---- Phase B: o = H @ W1^T ----
        #pragma unroll
        for (int mf = 0; mf < 2; ++mf)
            #pragma unroll
            for (int nt = 0; nt < 8; ++nt)
                #pragma unroll
                for (int u = 0; u < 4; ++u) acc[mf][nt][u] = 0.0f;

        #pragma unroll
        for (int kc = 0; kc < 8; ++kc) {
            int ko = kc * 32;
            uint32_t a0[4], a1[4];
            ldsm4(a0, aAddr[0] + ko);
            ldsm4(a1, aAddr[1] + ko);
            #pragma unroll
            for (int p = 0; p < 4; ++p) {
                uint32_t bb[4];
                ldsm4(bb, sbW + bOff[p] + ko);
                mma_f16(acc[0][2 * p],     a0[0], a0[1], a0[2], a0[3], bb[0], bb[1]);
                mma_f16(acc[1][2 * p],     a1[0], a1[1], a1[2], a1[3], bb[0], bb[1]);
                mma_f16(acc[0][2 * p + 1], a0[0], a0[1], a0[2], a0[3], bb[2], bb[3]);
                mma_f16(acc[1][2 * p + 1], a1[0], a1[1], a1[2], a1[3], bb[2], bb[3]);
            }
        }

        // ---- Epilogue: bias, GELU (0.5 folded into w2s), dot ----
        float tsum[4] = {0.f, 0.f, 0.f, 0.f};
        #pragma unroll
        for (int mf = 0; mf < 2; ++mf)
            #pragma unroll
            for (int nt = 0; nt < 8; ++nt) {
                int col = bcol + nt * 8 + 2 * c;
                float c0 = b1s[col], c1 = b1s[col + 1];
                float w0 = w2s[col], w1 = w2s[col + 1];
                tsum[mf * 2]     += gelu2x(acc[mf][nt][0] + c0) * w0
                                  + gelu2x(acc[mf][nt][1] + c1) * w1;
                tsum[mf * 2 + 1] += gelu2x(acc[mf][nt][2] + c0) * w0
                                  + gelu2x(acc[mf][nt][3] + c1) * w1;
            }
        #pragma unroll
        for (int off = 1; off <= 2; off <<= 1)
            #pragma unroll
            for (int lr = 0; lr < 4; ++lr)
                tsum[lr] += __shfl_xor_sync(0xffffffffu, tsum[lr], off);
        if (c == 0) {
            #pragma unroll
            for (int lr = 0; lr < 4; ++lr) {
                int row = arow + (lr >> 1) * 16 + (lr & 1) * 8 + g;
                redB[row * 2 + wk] = tsum[lr];
            }
        }
        barp(pb);

        // ---- C write: wk==0 warp of the pair handles its 32 rows ----
        if (wk == 0) {
            int row = arow + tx;
            int j = j0 + row;
            if (row < mrows && j < LL)
                Crow[j] = redB[row * 2] + redB[row * 2 + 1] + b2v;
        }
        // no trailing barrier: next-tile writes by this pair are ordered through
        // its own upcoming pair barriers; redB/redA reuse guarded likewise.
    }
}

// ---------------------------------------------------------------------------
// Kernel 3: out[b,i,j] = 0.5*(C[b,i,j] + C[b,j,i]) with smem tile transpose.
// ---------------------------------------------------------------------------
__global__ __launch_bounds__(256) void k3_sym(float* __restrict__ out)
{
    __shared__ float tA[32][33];
    __shared__ float tB[32][33];
    const int b  = blockIdx.z;
    const int i0 = blockIdx.y * 32, j0 = blockIdx.x * 32;
    const int tx = threadIdx.x & 31, ty = threadIdx.x >> 5;
    const float* Cb = g_C + (size_t)b * LL * LL;

    #pragma unroll
    for (int r = 0; r < 4; ++r) {
        int row = ty + r * 8;
        int gi = i0 + row, gj = j0 + tx;
        tA[row][tx] = (gi < LL && gj < LL) ? Cb[gi * LL + gj] : 0.f;
        int hi = j0 + row, hj = i0 + tx;
        tB[row][tx] = (hi < LL && hj < LL) ? Cb[hi * LL + hj] : 0.f;
    }
    __syncthreads();

    float* Ob = out + (size_t)b * LL * LL;
    #pragma unroll
    for (int r = 0; r < 4; ++r) {
        int row = ty + r * 8;
        int gi = i0 + row, gj = j0 + tx;
        if (gi < LL && gj < LL)
            Ob[gi * LL + gj] = 0.5f * (tA[row][tx] + tB[tx][row]);
    }
}

// ---------------------------------------------------------------------------
extern "C" void kernel_launch(void* const* d_in, const int* in_sizes, int n_in,
                              void* d_out, int out_size)
{
    (void)in_sizes; (void)n_in; (void)out_size;
    const float* x     = (const float*)d_in[0];
    const float* W_bil = (const float*)d_in[1];
    const float* b_bil = (const float*)d_in[2];
    const float* ln_g  = (const float*)d_in[3];
    const float* ln_b  = (const float*)d_in[4];
    const float* W1    = (const float*)d_in[5];
    const float* b1    = (const float*)d_in[6];
    const float* w2    = (const float*)d_in[7];
    const float* b2    = (const float*)d_in[8];
    float* out = (float*)d_out;

    cudaFuncSetAttribute(k1_tmp,   cudaFuncAttributeMaxDynamicSharedMemorySize, K1_SMEM);
    cudaFuncSetAttribute(k2_fused, cudaFuncAttributeMaxDynamicSharedMemorySize, K2_SMEM);

    k0_transpose<<<128, 256>>>(W_bil);
    k0x_convert<<<(BB * 512 * 64 + 255) / 256, 256>>>(x);
    dim3 g1(128, (NBI + 127) / 128);   // 128 x 7
    k1_tmp<<<g1, 256, K1_SMEM>>>();
    k2_fused<<<NBI, 256, K2_SMEM>>>(b_bil, ln_g, ln_b, W1, b1, w2, b2);

    dim3 g3((LL + 31) / 32, (LL + 31) / 32, BB);   // 13 x 13 x 2
    k3_sym<<<g3, 256>>>(out);
}